// round 2
// baseline (speedup 1.0000x reference)
#include <cuda_runtime.h>
#include <math.h>

// Problem dims (fixed by the reference)
#define NB    16
#define NL    1536
#define ND    512
#define NDFF  2048
#define NTOPK 7
#define NBLD  (NB*NL*ND)          // 12,582,912

// ---------------- scratch (device globals: allocation-free rule) -------------
__device__ float g_q[NBLD];
__device__ float g_k[NBLD];
__device__ float g_v[NBLD];
__device__ float g_o[NBLD];
__device__ float g_xs[NBLD];
__device__ float g_xs2[NBLD];
__device__ float g_xw1[NBLD];
__device__ float g_tmp[NBLD];
__device__ float g_h[50331648];   // 16*1536*2048
__device__ float g_mean[NB*NL];
__device__ int   g_idx[NTOPK];
__device__ float g_wt[NB*NTOPK];

// ---------------- SGEMM: C[m,n] = act( A[m,:]·W[n,:] + bias[n] + R[m,n] ) ----
// A is [M,K] row-major; row index can be circularly shifted along L per batch
// (token_embed circular conv). W element (n,k) at W[n*wsN + k*wsK].
__global__ void __launch_bounds__(256)
sgemm_kernel(const float* __restrict__ A, const float* __restrict__ W,
             const float* __restrict__ bias, const float* R, float* C,
             int M, int N, int K, int wsN, int wsK, int shift, int doRelu)
{
    __shared__ float As[16][64];
    __shared__ float Ws[16][64];
    int tid = threadIdx.x;
    int tr  = tid >> 4;          // 0..15
    int tc  = tid & 15;          // 0..15
    int m0  = blockIdx.y << 6;
    int n0  = blockIdx.x << 6;

    // A-tile load mapping: one float4 per thread
    int lrow = tid >> 2;          // 0..63
    int kq   = (tid & 3) << 2;    // 0,4,8,12
    int am   = m0 + lrow;
    int arow;
    if (shift == 0) {
        arow = am;
    } else {
        int b = am / NL;
        int t = am - b * NL + shift;
        if (t < 0)   t += NL;
        if (t >= NL) t -= NL;
        arow = b * NL + t;
    }
    const float* Ap = A + (size_t)arow * K + kq;
    const float* Wp = W + (size_t)(n0 + lrow) * wsN + kq;   // wsK==1 fast path

    float acc[4][4];
    #pragma unroll
    for (int i = 0; i < 4; i++)
        #pragma unroll
        for (int j = 0; j < 4; j++) acc[i][j] = 0.f;

    for (int k0 = 0; k0 < K; k0 += 16) {
        float4 av = *reinterpret_cast<const float4*>(Ap + k0);
        As[kq+0][lrow] = av.x; As[kq+1][lrow] = av.y;
        As[kq+2][lrow] = av.z; As[kq+3][lrow] = av.w;
        if (wsK == 1) {
            float4 wv = *reinterpret_cast<const float4*>(Wp + k0);
            Ws[kq+0][lrow] = wv.x; Ws[kq+1][lrow] = wv.y;
            Ws[kq+2][lrow] = wv.z; Ws[kq+3][lrow] = wv.w;
        } else {
            #pragma unroll
            for (int j = 0; j < 4; j++) {
                int e  = tid + (j << 8);
                int kk = e & 15;
                int nn = e >> 4;
                Ws[kk][nn] = W[(size_t)(n0+nn)*wsN + (size_t)(k0+kk)*wsK];
            }
        }
        __syncthreads();
        #pragma unroll
        for (int kk = 0; kk < 16; kk++) {
            float4 aa = *reinterpret_cast<const float4*>(&As[kk][tr << 2]);
            float4 bb = *reinterpret_cast<const float4*>(&Ws[kk][tc << 2]);
            acc[0][0] += aa.x*bb.x; acc[0][1] += aa.x*bb.y; acc[0][2] += aa.x*bb.z; acc[0][3] += aa.x*bb.w;
            acc[1][0] += aa.y*bb.x; acc[1][1] += aa.y*bb.y; acc[1][2] += aa.y*bb.z; acc[1][3] += aa.y*bb.w;
            acc[2][0] += aa.z*bb.x; acc[2][1] += aa.z*bb.y; acc[2][2] += aa.z*bb.z; acc[2][3] += aa.z*bb.w;
            acc[3][0] += aa.w*bb.x; acc[3][1] += aa.w*bb.y; acc[3][2] += aa.w*bb.z; acc[3][3] += aa.w*bb.w;
        }
        __syncthreads();
    }

    #pragma unroll
    for (int i = 0; i < 4; i++) {
        int mm = m0 + (tr << 2) + i;
        #pragma unroll
        for (int j = 0; j < 4; j++) {
            int nn = n0 + (tc << 2) + j;
            float vv = acc[i][j];
            if (bias) vv += bias[nn];
            if (R)    vv += R[(size_t)mm * N + nn];
            if (doRelu) vv = fmaxf(vv, 0.f);
            C[(size_t)mm * N + nn] = vv;
        }
    }
}

// ---------------- correlation: mean_value[b,tau] += (1/D)*diag-sums of Q·K^T -
__global__ void __launch_bounds__(256)
corr_kernel(const float* __restrict__ Q, const float* __restrict__ Kmat)
{
    __shared__ float As[16][64];
    __shared__ float Ws[16][64];
    __shared__ float bins[128];
    int b = blockIdx.z;
    const float* A = Q    + (size_t)b * NL * ND;
    const float* W = Kmat + (size_t)b * NL * ND;
    int tid = threadIdx.x;
    int tr = tid >> 4, tc = tid & 15;
    int t0 = blockIdx.y << 6, s0 = blockIdx.x << 6;
    int lrow = tid >> 2, kq = (tid & 3) << 2;
    const float* Ap = A + (size_t)(t0 + lrow) * ND + kq;
    const float* Wp = W + (size_t)(s0 + lrow) * ND + kq;

    float acc[4][4];
    #pragma unroll
    for (int i = 0; i < 4; i++)
        #pragma unroll
        for (int j = 0; j < 4; j++) acc[i][j] = 0.f;

    for (int k0 = 0; k0 < ND; k0 += 16) {
        float4 av = *reinterpret_cast<const float4*>(Ap + k0);
        float4 wv = *reinterpret_cast<const float4*>(Wp + k0);
        As[kq+0][lrow] = av.x; As[kq+1][lrow] = av.y;
        As[kq+2][lrow] = av.z; As[kq+3][lrow] = av.w;
        Ws[kq+0][lrow] = wv.x; Ws[kq+1][lrow] = wv.y;
        Ws[kq+2][lrow] = wv.z; Ws[kq+3][lrow] = wv.w;
        __syncthreads();
        #pragma unroll
        for (int kk = 0; kk < 16; kk++) {
            float4 aa = *reinterpret_cast<const float4*>(&As[kk][tr << 2]);
            float4 bb = *reinterpret_cast<const float4*>(&Ws[kk][tc << 2]);
            acc[0][0] += aa.x*bb.x; acc[0][1] += aa.x*bb.y; acc[0][2] += aa.x*bb.z; acc[0][3] += aa.x*bb.w;
            acc[1][0] += aa.y*bb.x; acc[1][1] += aa.y*bb.y; acc[1][2] += aa.y*bb.z; acc[1][3] += aa.y*bb.w;
            acc[2][0] += aa.z*bb.x; acc[2][1] += aa.z*bb.y; acc[2][2] += aa.z*bb.z; acc[2][3] += aa.z*bb.w;
            acc[3][0] += aa.w*bb.x; acc[3][1] += aa.w*bb.y; acc[3][2] += aa.w*bb.z; acc[3][3] += aa.w*bb.w;
        }
        __syncthreads();
    }

    for (int e = tid; e < 127; e += 256) bins[e] = 0.f;
    __syncthreads();
    // per-thread diagonal pre-reduction: diff = 4*(tr-tc) + (i-j)
    float dsum[7] = {0,0,0,0,0,0,0};
    #pragma unroll
    for (int i = 0; i < 4; i++)
        #pragma unroll
        for (int j = 0; j < 4; j++) dsum[i - j + 3] += acc[i][j];
    int basel = ((tr - tc) << 2) + 63;
    #pragma unroll
    for (int dd = -3; dd <= 3; dd++) atomicAdd(&bins[basel + dd], dsum[dd + 3]);
    __syncthreads();
    for (int e = tid; e < 127; e += 256) {
        int tau = t0 - s0 + e - 63;
        tau %= NL; if (tau < 0) tau += NL;
        atomicAdd(&g_mean[b * NL + tau], bins[e] * (1.f / (float)ND));
    }
}

// ---------------- top-7 over batch-mean, softmax weights per batch ----------
__global__ void topk_kernel()
{
    __shared__ float gv[NL];
    __shared__ float rv[512];
    __shared__ int   ri[512];
    __shared__ int   sidx[NTOPK];
    int tid = threadIdx.x;
    for (int t = tid; t < NL; t += 512) {
        float s = 0.f;
        for (int b = 0; b < NB; b++) s += g_mean[b * NL + t];
        gv[t] = s;
    }
    __syncthreads();
    for (int it = 0; it < NTOPK; it++) {
        float bv = -INFINITY; int bi = 0x7fffffff;
        for (int t = tid; t < NL; t += 512) {
            float v = gv[t];
            if (v > bv || (v == bv && t < bi)) { bv = v; bi = t; }
        }
        rv[tid] = bv; ri[tid] = bi;
        __syncthreads();
        for (int s = 256; s > 0; s >>= 1) {
            if (tid < s) {
                if (rv[tid+s] > rv[tid] || (rv[tid+s] == rv[tid] && ri[tid+s] < ri[tid])) {
                    rv[tid] = rv[tid+s]; ri[tid] = ri[tid+s];
                }
            }
            __syncthreads();
        }
        if (tid == 0) { sidx[it] = ri[0]; gv[ri[0]] = -INFINITY; }
        __syncthreads();
    }
    if (tid < NTOPK) g_idx[tid] = sidx[tid];
    if (tid < NB) {
        float vals[NTOPK];
        float mx = -INFINITY;
        for (int i = 0; i < NTOPK; i++) {
            vals[i] = g_mean[tid * NL + sidx[i]];
            mx = fmaxf(mx, vals[i]);
        }
        float s = 0.f;
        for (int i = 0; i < NTOPK; i++) { vals[i] = expf(vals[i] - mx); s += vals[i]; }
        float inv = 1.f / s;
        for (int i = 0; i < NTOPK; i++) g_wt[tid * NTOPK + i] = vals[i] * inv;
    }
}

// ---------------- time-delay aggregation: O = sum_i w[b,i]*roll(V, idx[i]) ---
__global__ void roll_kernel(const float* __restrict__ V, float* __restrict__ O)
{
    size_t e = (size_t)blockIdx.x * blockDim.x + threadIdx.x;
    if (e >= (size_t)NBLD) return;
    int d = (int)(e & (ND - 1));
    size_t row = e >> 9;                 // ND = 512 = 2^9
    int b = (int)(row / NL);
    int t = (int)(row - (size_t)b * NL);
    float s = 0.f;
    #pragma unroll
    for (int i = 0; i < NTOPK; i++) {
        int tt = t + g_idx[i];
        if (tt >= NL) tt -= NL;
        s += g_wt[b * NTOPK + i] * V[((size_t)b * NL + tt) * ND + d];
    }
    O[e] = s;
}

// ---------------- series_decomp: out = x - movavg25(x), replicate-padded ----
__global__ void decomp_kernel(const float* __restrict__ X, float* __restrict__ O)
{
    size_t e = (size_t)blockIdx.x * blockDim.x + threadIdx.x;
    if (e >= (size_t)NBLD) return;
    int d = (int)(e & (ND - 1));
    size_t row = e >> 9;
    int b = (int)(row / NL);
    int t = (int)(row - (size_t)b * NL);
    const float* Xb = X + (size_t)b * NL * ND + d;
    float s = 0.f;
    #pragma unroll
    for (int u = -12; u <= 12; u++) {
        int tt = t + u;
        tt = tt < 0 ? 0 : (tt >= NL ? NL - 1 : tt);
        s += Xb[(size_t)tt * ND];
    }
    O[e] = X[e] - s * (1.f / 25.f);
}

// ---------------- host orchestration ----------------------------------------
static inline void launch_gemm(const float* A, const float* W, const float* bias,
                               const float* R, float* C, int M, int N, int K,
                               int wsN, int wsK, int shift, int relu)
{
    dim3 grid(N / 64, M / 64);
    sgemm_kernel<<<grid, 256>>>(A, W, bias, R, C, M, N, K, wsN, wsK, shift, relu);
}

extern "C" void kernel_launch(void* const* d_in, const int* in_sizes, int n_in,
                              void* d_out, int out_size)
{
    const float* x_s      = (const float*)d_in[0];
    const float* x_w      = (const float*)d_in[1];
    const float* wc1_W    = (const float*)d_in[2];
    const float* wc1_b    = (const float*)d_in[3];
    const float* wc2_W    = (const float*)d_in[4];
    const float* wc2_b    = (const float*)d_in[5];
    const float* attn_W   = (const float*)d_in[6];
    const float* attn_b   = (const float*)d_in[7];
    const float* wc1_proj = (const float*)d_in[8];
    const float* wc2_proj = (const float*)d_in[9];
    const float* conv1_W  = (const float*)d_in[10];
    const float* conv2_W  = (const float*)d_in[11];
    float* out = (float*)d_out;

    float *q, *k, *v, *o, *xs, *xs2, *xw1, *tmp, *h, *mean;
    cudaGetSymbolAddress((void**)&q,    g_q);
    cudaGetSymbolAddress((void**)&k,    g_k);
    cudaGetSymbolAddress((void**)&v,    g_v);
    cudaGetSymbolAddress((void**)&o,    g_o);
    cudaGetSymbolAddress((void**)&xs,   g_xs);
    cudaGetSymbolAddress((void**)&xs2,  g_xs2);
    cudaGetSymbolAddress((void**)&xw1,  g_xw1);
    cudaGetSymbolAddress((void**)&tmp,  g_tmp);
    cudaGetSymbolAddress((void**)&h,    g_h);
    cudaGetSymbolAddress((void**)&mean, g_mean);

    const int M  = NB * NL;
    const int DD = ND * ND;
    const int nEltBlocks = (NBLD + 255) / 256;
    dim3 corrGrid(NL / 64, NL / 64, NB);

    // ---- stage A: x_s += attn(q=x_w, k=v=x_s, wc1) --------------------------
    launch_gemm(x_w, wc1_W,          wc1_b,          nullptr, q, M, ND, ND, ND, 1, 0, 0);
    launch_gemm(x_s, wc1_W + DD,     wc1_b + ND,     nullptr, k, M, ND, ND, ND, 1, 0, 0);
    launch_gemm(x_s, wc1_W + 2*DD,   wc1_b + 2*ND,   nullptr, v, M, ND, ND, ND, 1, 0, 0);
    cudaMemsetAsync(mean, 0, NB * NL * sizeof(float), 0);
    corr_kernel<<<corrGrid, 256>>>(q, k);
    topk_kernel<<<1, 512>>>();
    roll_kernel<<<nEltBlocks, 256>>>(v, o);
    launch_gemm(o, wc1_W + 3*DD, wc1_b + 3*ND, x_s, xs, M, ND, ND, ND, 1, 0, 0);

    // ---- stage B: xw1 = token_embed(x_w, wc1_proj) --------------------------
    launch_gemm(x_w, wc1_proj + 0, nullptr, nullptr, xw1, M, ND, ND, 3*ND, 3, -1, 0);
    launch_gemm(x_w, wc1_proj + 1, nullptr, xw1,     xw1, M, ND, ND, 3*ND, 3,  0, 0);
    launch_gemm(x_w, wc1_proj + 2, nullptr, xw1,     xw1, M, ND, ND, 3*ND, 3,  1, 0);

    // ---- stage C: xs += attn(xs, xs, xs, attn_W) ----------------------------
    launch_gemm(xs, attn_W,          attn_b,          nullptr, q, M, ND, ND, ND, 1, 0, 0);
    launch_gemm(xs, attn_W + DD,     attn_b + ND,     nullptr, k, M, ND, ND, ND, 1, 0, 0);
    launch_gemm(xs, attn_W + 2*DD,   attn_b + 2*ND,   nullptr, v, M, ND, ND, ND, 1, 0, 0);
    cudaMemsetAsync(mean, 0, NB * NL * sizeof(float), 0);
    corr_kernel<<<corrGrid, 256>>>(q, k);
    topk_kernel<<<1, 512>>>();
    roll_kernel<<<nEltBlocks, 256>>>(v, o);
    launch_gemm(o, attn_W + 3*DD, attn_b + 3*ND, xs, xs, M, ND, ND, ND, 1, 0, 0);

    // ---- stage D: xs2 = series_decomp(xs) -----------------------------------
    decomp_kernel<<<nEltBlocks, 256>>>(xs, xs2);

    // ---- stage E: xs2 += attn(q=xw1, k=v=xs2, wc2) --------------------------
    launch_gemm(xw1, wc2_W,          wc2_b,          nullptr, q, M, ND, ND, ND, 1, 0, 0);
    launch_gemm(xs2, wc2_W + DD,     wc2_b + ND,     nullptr, k, M, ND, ND, ND, 1, 0, 0);
    launch_gemm(xs2, wc2_W + 2*DD,   wc2_b + 2*ND,   nullptr, v, M, ND, ND, ND, 1, 0, 0);
    cudaMemsetAsync(mean, 0, NB * NL * sizeof(float), 0);
    corr_kernel<<<corrGrid, 256>>>(q, k);
    topk_kernel<<<1, 512>>>();
    roll_kernel<<<nEltBlocks, 256>>>(v, o);
    launch_gemm(o, wc2_W + 3*DD, wc2_b + 3*ND, xs2, xs2, M, ND, ND, ND, 1, 0, 0);

    // ---- stage F: x_w_new = token_embed(xw1, wc2_proj) -> second output half
    float* out2 = out + NBLD;
    launch_gemm(xw1, wc2_proj + 0, nullptr, nullptr, out2, M, ND, ND, 3*ND, 3, -1, 0);
    launch_gemm(xw1, wc2_proj + 1, nullptr, out2,    out2, M, ND, ND, 3*ND, 3,  0, 0);
    launch_gemm(xw1, wc2_proj + 2, nullptr, out2,    out2, M, ND, ND, 3*ND, 3,  1, 0);

    // ---- stage G: FFN + final series_decomp -> first output half ------------
    launch_gemm(xs2, conv1_W, nullptr, nullptr, h,   M, NDFF, ND,  ND,   1, 0, 1);
    launch_gemm(h,   conv2_W, nullptr, xs2,     tmp, M, ND,   NDFF, NDFF, 1, 0, 0);
    decomp_kernel<<<nEltBlocks, 256>>>(tmp, out);
}

// round 4
// speedup vs baseline: 2.7521x; 2.7521x over previous
#include <cuda_runtime.h>
#include <cuda_bf16.h>
#include <cstdint>
#include <math.h>

#define NB    16
#define NL    1536
#define ND    512
#define NDFF  2048
#define NTOPK 7
#define NBLD  (NB*NL*ND)
#define NH    (NB*NL*NDFF)
#define DDW   262144            // 512*512

// ------------------------------- scratch ------------------------------------
__device__ float g_v[NBLD];
__device__ float g_xs[NBLD];
__device__ float g_xs2[NBLD];
__device__ float g_tmp[NBLD];
__device__ float g_mean[NB*NL];
__device__ int   g_idx[NTOPK];
__device__ float g_wt[NB*NTOPK];

// bf16 hi/lo arenas
__device__ __nv_bfloat16 g_wh[26*DDW], g_wl[26*DDW];
__device__ __nv_bfloat16 hXW[NBLD],  lXW[NBLD];
__device__ __nv_bfloat16 hXSI[NBLD], lXSI[NBLD];
__device__ __nv_bfloat16 hXW1[NBLD], lXW1[NBLD];
__device__ __nv_bfloat16 hQ[NBLD],   lQ[NBLD];
__device__ __nv_bfloat16 hK[NBLD],   lK[NBLD];
__device__ __nv_bfloat16 hO[NBLD],   lO[NBLD];
__device__ __nv_bfloat16 hXS[NBLD],  lXS[NBLD];
__device__ __nv_bfloat16 hXS2[NBLD], lXS2[NBLD];
__device__ __nv_bfloat16 hXSB[NBLD], lXSB[NBLD];
__device__ __nv_bfloat16 hH[NH],     lH[NH];

// ------------------------------- helpers -------------------------------------
__device__ __forceinline__ uint32_t smem_u32(const void* p){
    uint32_t a;
    asm("{ .reg .u64 t; cvta.to.shared.u64 t, %1; cvt.u32.u64 %0, t; }":"=r"(a):"l"(p));
    return a;
}
__device__ __forceinline__ void cp16(uint32_t s, const void* g){
    asm volatile("cp.async.cg.shared.global [%0], [%1], 16;"::"r"(s),"l"(g));
}
__device__ __forceinline__ void cp_commit(){
    asm volatile("cp.async.commit_group;":::"memory");
}
__device__ __forceinline__ void ldm4(uint32_t* r, uint32_t a){
    asm volatile("ldmatrix.sync.aligned.m8n8.x4.shared.b16 {%0,%1,%2,%3}, [%4];"
        : "=r"(r[0]),"=r"(r[1]),"=r"(r[2]),"=r"(r[3]) : "r"(a));
}
__device__ __forceinline__ void mma16816(float* c, const uint32_t* a, uint32_t b0, uint32_t b1){
    asm volatile("mma.sync.aligned.m16n8k16.row.col.f32.bf16.bf16.f32 "
        "{%0,%1,%2,%3},{%4,%5,%6,%7},{%8,%9},{%0,%1,%2,%3};"
        : "+f"(c[0]),"+f"(c[1]),"+f"(c[2]),"+f"(c[3])
        : "r"(a[0]),"r"(a[1]),"r"(a[2]),"r"(a[3]), "r"(b0),"r"(b1));
}
#define SWZ(o) ((o) ^ (((o) >> 3) & 0x70))

#define STG_B   65536u
#define SMEM_SZ (2*STG_B)

// issue one stage of global->smem copies (Ah,Al,Bh,Bl sub-tiles, 128x64 bf16 ea.)
#define LOADC(stage, k0) do{ \
    uint32_t sp_ = sb + (stage)*STG_B; \
    _Pragma("unroll") \
    for (int i_ = 0; i_ < 4; i_++){ \
        cp16(sp_ + soff[i_],          Ah + aoff[i_] + (k0)); \
        cp16(sp_ + 16384 + soff[i_],  Al + aoff[i_] + (k0)); \
        cp16(sp_ + 32768 + soff[i_],  Bh + boff[i_] + (k0)); \
        cp16(sp_ + 49152 + soff[i_],  Bl + boff[i_] + (k0)); \
    } \
    cp_commit(); \
}while(0)

// one 64-wide K chunk of 3-term MMAs (warp tile 64x32)
#define COMPUTE_CHUNK(stg_) do{ \
    uint32_t stg = (stg_)*STG_B; \
    _Pragma("unroll") \
    for (int ks = 0; ks < 4; ks++){ \
        uint32_t ah[4][4], al[4][4], bh[2][4], bl[2][4]; \
        uint32_t ca = ((((ks<<1)|cq) ^ sA) << 4); \
        uint32_t cb = ((((ks<<1)|cq) ^ sB) << 4); \
        _Pragma("unroll") \
        for (int mi = 0; mi < 4; mi++){ \
            uint32_t ad = sb + stg + aB[mi] + ca; \
            ldm4(ah[mi], ad); \
            ldm4(al[mi], ad + 16384); \
        } \
        _Pragma("unroll") \
        for (int nj = 0; nj < 2; nj++){ \
            uint32_t bd = sb + stg + bB[nj] + cb + 32768; \
            ldm4(bh[nj], bd); \
            ldm4(bl[nj], bd + 16384); \
        } \
        _Pragma("unroll") \
        for (int mi = 0; mi < 4; mi++){ \
            _Pragma("unroll") \
            for (int ni = 0; ni < 4; ni++){ \
                uint32_t g = ni >> 1, s = ni & 1; \
                mma16816(acc[mi][ni], ah[mi], bh[g][s], bh[g][s+2]); \
                mma16816(acc[mi][ni], ah[mi], bl[g][s], bl[g][s+2]); \
                mma16816(acc[mi][ni], al[mi], bh[g][s], bh[g][s+2]); \
            } \
        } \
    } \
}while(0)

// shared prologue: global-load offsets + ldmatrix bases + pipelined mainloop
#define GEMM_MAINLOOP(SHIFT_EXPR) \
    uint32_t sb = smem_u32(smem); \
    int tid = threadIdx.x, wid = tid >> 5, lane = tid & 31; \
    size_t aoff[4], boff[4]; \
    uint32_t soff[4]; \
    _Pragma("unroll") \
    for (int i = 0; i < 4; i++){ \
        int idx = tid + (i << 8); \
        int r = idx >> 3, u = idx & 7; \
        int arow; { SHIFT_EXPR } \
        aoff[i] = (size_t)arow * K + u * 8; \
        boff[i] = (size_t)(n0 + r) * K + u * 8; \
        soff[i] = SWZ((uint32_t)(r * 128 + u * 16)); \
    } \
    int wm = wid >> 2, wn = wid & 3; \
    int rowA = (wm << 6) + (lane & 15); \
    int rowB = (wn << 5) + (lane & 15); \
    uint32_t sA = rowA & 7, sB = rowB & 7, cq = lane >> 4; \
    uint32_t aB[4], bB[2]; \
    _Pragma("unroll") for (int mi = 0; mi < 4; mi++) aB[mi] = (uint32_t)(rowA + (mi<<4)) * 128; \
    _Pragma("unroll") for (int nj = 0; nj < 2; nj++) bB[nj] = (uint32_t)(rowB + (nj<<4)) * 128; \
    float acc[4][4][4]; \
    _Pragma("unroll") for (int mi = 0; mi < 4; mi++) \
        _Pragma("unroll") for (int ni = 0; ni < 4; ni++) \
            _Pragma("unroll") for (int e2 = 0; e2 < 4; e2++) acc[mi][ni][e2] = 0.f; \
    int nch = K >> 6; \
    LOADC(0, 0); \
    for (int c = 0; c < nch; c++){ \
        if (c + 1 < nch){ \
            LOADC((c+1)&1, (size_t)(c+1) << 6); \
            asm volatile("cp.async.wait_group 1;":::"memory"); \
        } else { \
            asm volatile("cp.async.wait_group 0;":::"memory"); \
        } \
        __syncthreads(); \
        COMPUTE_CHUNK(c & 1); \
        __syncthreads(); \
    }

// ------------------------------- GEMM kernel ---------------------------------
// C[m,n] = act( sum_k A[m,k]*W[n,k] + bias[n] + R[m,n] ); A rows optionally
// circularly shifted along L (token-embed). A,W are bf16 hi/lo pairs.
__global__ void __launch_bounds__(256,1)
gemm_bf(const __nv_bfloat16* __restrict__ Ah, const __nv_bfloat16* __restrict__ Al,
        const __nv_bfloat16* __restrict__ Bh, const __nv_bfloat16* __restrict__ Bl,
        const float* __restrict__ bias, const float* __restrict__ R,
        float* Cf, __nv_bfloat16* Ch, __nv_bfloat16* Cl,
        int N, int K, int shift, int relu)
{
    extern __shared__ char smem[];
    int m0 = blockIdx.y << 7, n0 = blockIdx.x << 7;

    GEMM_MAINLOOP(
        int am = m0 + r;
        if (shift == 0) arow = am;
        else {
            int b = am / NL;
            int t = am - b * NL + shift;
            if (t < 0) t += NL; if (t >= NL) t -= NL;
            arow = b * NL + t;
        }
    )

    // ---- epilogue: fragments -> global --------------------------------------
    int gm = m0 + (wm << 6) + (lane >> 2);
    int gn = n0 + (wn << 5) + ((lane & 3) << 1);
    #pragma unroll
    for (int mi = 0; mi < 4; mi++){
        #pragma unroll
        for (int ni = 0; ni < 4; ni++){
            #pragma unroll
            for (int hh = 0; hh < 2; hh++){
                int rr = gm + (mi << 4) + hh * 8;
                int cc = gn + (ni << 3);
                float v0 = acc[mi][ni][hh*2+0];
                float v1 = acc[mi][ni][hh*2+1];
                if (bias){ v0 += bias[cc]; v1 += bias[cc+1]; }
                size_t o = (size_t)rr * N + cc;
                if (R){ float2 r2 = *reinterpret_cast<const float2*>(R + o); v0 += r2.x; v1 += r2.y; }
                if (relu){ v0 = fmaxf(v0, 0.f); v1 = fmaxf(v1, 0.f); }
                if (Cf) *reinterpret_cast<float2*>(Cf + o) = make_float2(v0, v1);
                if (Ch){
                    __nv_bfloat16 h0 = __float2bfloat16(v0), h1 = __float2bfloat16(v1);
                    *reinterpret_cast<__nv_bfloat162*>(Ch + o) = __nv_bfloat162{h0, h1};
                    *reinterpret_cast<__nv_bfloat162*>(Cl + o) = __nv_bfloat162{
                        __float2bfloat16(v0 - __bfloat162float(h0)),
                        __float2bfloat16(v1 - __bfloat162float(h1))};
                }
            }
        }
    }
}

// --------------------------- correlation kernel ------------------------------
// per batch b: g_mean[b,tau] += (1/512)*sum over (t,s): (t-s)%L==tau of <Q_t,K_s>
__global__ void __launch_bounds__(256,1)
corr_bf(const __nv_bfloat16* __restrict__ Qh, const __nv_bfloat16* __restrict__ Ql,
        const __nv_bfloat16* __restrict__ Kh, const __nv_bfloat16* __restrict__ Kl)
{
    extern __shared__ char smem[];
    int bb = blockIdx.z;
    size_t base = (size_t)bb * NL * ND;
    int m0 = blockIdx.y << 7, n0 = blockIdx.x << 7;
    const int K = ND;
    const __nv_bfloat16 *Ah = Qh + base, *Al = Ql + base;
    const __nv_bfloat16 *Bh = Kh + base, *Bl = Kl + base;

    GEMM_MAINLOOP( arow = m0 + r; )

    // ---- epilogue: anti-diagonal reduction ----------------------------------
    float* bins = reinterpret_cast<float*>(smem);
    if (tid < 255) bins[tid] = 0.f;
    __syncthreads();

    int lm = (wm << 6) + (lane >> 2);
    int ln = (wn << 5) + ((lane & 3) << 1);
    #pragma unroll
    for (int mi = 0; mi < 4; mi++){
        #pragma unroll
        for (int ni = 0; ni < 4; ni++){
            #pragma unroll
            for (int hh = 0; hh < 2; hh++){
                int rr = lm + (mi << 4) + hh * 8;
                int cc = ln + (ni << 3);
                atomicAdd(&bins[rr - cc + 127],     acc[mi][ni][hh*2+0]);
                atomicAdd(&bins[rr - cc - 1 + 127], acc[mi][ni][hh*2+1]);
            }
        }
    }
    __syncthreads();
    if (tid < 255){
        int tau = m0 - n0 + tid - 127;
        tau %= NL; if (tau < 0) tau += NL;
        atomicAdd(&g_mean[bb * NL + tau], bins[tid] * (1.f / 512.f));
    }
}

// ------------------------------ small kernels --------------------------------
__global__ void cvt_kernel(const float* __restrict__ x, __nv_bfloat16* __restrict__ h,
                           __nv_bfloat16* __restrict__ l, int n4)
{
    int i = blockIdx.x * blockDim.x + threadIdx.x;
    if (i >= n4) return;
    float4 v = reinterpret_cast<const float4*>(x)[i];
    __nv_bfloat16 h0=__float2bfloat16(v.x), h1=__float2bfloat16(v.y),
                  h2=__float2bfloat16(v.z), h3=__float2bfloat16(v.w);
    __nv_bfloat162* hp = reinterpret_cast<__nv_bfloat162*>(h);
    __nv_bfloat162* lp = reinterpret_cast<__nv_bfloat162*>(l);
    hp[2*i]   = __nv_bfloat162{h0, h1};
    hp[2*i+1] = __nv_bfloat162{h2, h3};
    lp[2*i]   = __nv_bfloat162{__float2bfloat16(v.x - __bfloat162float(h0)),
                               __float2bfloat16(v.y - __bfloat162float(h1))};
    lp[2*i+1] = __nv_bfloat162{__float2bfloat16(v.z - __bfloat162float(h2)),
                               __float2bfloat16(v.w - __bfloat162float(h3))};
}

// de-stride token-embed weights: dst[n*512+k] = src[n*1536 + k*3]
__global__ void cvt_proj_kernel(const float* __restrict__ src,
                                __nv_bfloat16* __restrict__ h, __nv_bfloat16* __restrict__ l)
{
    int e = blockIdx.x * blockDim.x + threadIdx.x;
    if (e >= DDW) return;
    int n = e >> 9, k = e & 511;
    float v = src[n * 1536 + k * 3];
    __nv_bfloat16 hh = __float2bfloat16(v);
    h[e] = hh;
    l[e] = __float2bfloat16(v - __bfloat162float(hh));
}

__global__ void topk_kernel()
{
    __shared__ float gv[NL];
    __shared__ float rv[512];
    __shared__ int   ri[512];
    __shared__ int   sidx[NTOPK];
    int tid = threadIdx.x;
    for (int t = tid; t < NL; t += 512) {
        float s = 0.f;
        for (int b = 0; b < NB; b++) s += g_mean[b * NL + t];
        gv[t] = s;
    }
    __syncthreads();
    for (int it = 0; it < NTOPK; it++) {
        float bv = -INFINITY; int bi = 0x7fffffff;
        for (int t = tid; t < NL; t += 512) {
            float v = gv[t];
            if (v > bv || (v == bv && t < bi)) { bv = v; bi = t; }
        }
        rv[tid] = bv; ri[tid] = bi;
        __syncthreads();
        for (int s = 256; s > 0; s >>= 1) {
            if (tid < s) {
                if (rv[tid+s] > rv[tid] || (rv[tid+s] == rv[tid] && ri[tid+s] < ri[tid])) {
                    rv[tid] = rv[tid+s]; ri[tid] = ri[tid+s];
                }
            }
            __syncthreads();
        }
        if (tid == 0) { sidx[it] = ri[0]; gv[ri[0]] = -INFINITY; }
        __syncthreads();
    }
    if (tid < NTOPK) g_idx[tid] = sidx[tid];
    if (tid < NB) {
        float vals[NTOPK];
        float mx = -INFINITY;
        for (int i = 0; i < NTOPK; i++) {
            vals[i] = g_mean[tid * NL + sidx[i]];
            mx = fmaxf(mx, vals[i]);
        }
        float s = 0.f;
        for (int i = 0; i < NTOPK; i++) { vals[i] = expf(vals[i] - mx); s += vals[i]; }
        float inv = 1.f / s;
        for (int i = 0; i < NTOPK; i++) g_wt[tid * NTOPK + i] = vals[i] * inv;
    }
}

__global__ void roll_kernel(const float* __restrict__ V,
                            __nv_bfloat16* __restrict__ Oh, __nv_bfloat16* __restrict__ Ol)
{
    size_t e = (size_t)blockIdx.x * blockDim.x + threadIdx.x;
    if (e >= (size_t)NBLD) return;
    int d = (int)(e & (ND - 1));
    size_t row = e >> 9;
    int b = (int)(row / NL);
    int t = (int)(row - (size_t)b * NL);
    float s = 0.f;
    #pragma unroll
    for (int i = 0; i < NTOPK; i++) {
        int tt = t + g_idx[i];
        if (tt >= NL) tt -= NL;
        s += g_wt[b * NTOPK + i] * V[((size_t)b * NL + tt) * ND + d];
    }
    __nv_bfloat16 h = __float2bfloat16(s);
    Oh[e] = h;
    Ol[e] = __float2bfloat16(s - __bfloat162float(h));
}

__global__ void decomp_kernel(const float* __restrict__ X, float* __restrict__ Of,
                              __nv_bfloat16* Oh, __nv_bfloat16* Ol)
{
    size_t e = (size_t)blockIdx.x * blockDim.x + threadIdx.x;
    if (e >= (size_t)NBLD) return;
    int d = (int)(e & (ND - 1));
    size_t row = e >> 9;
    int b = (int)(row / NL);
    int t = (int)(row - (size_t)b * NL);
    const float* Xb = X + (size_t)b * NL * ND + d;
    float s = 0.f;
    #pragma unroll
    for (int u = -12; u <= 12; u++) {
        int tt = t + u;
        tt = tt < 0 ? 0 : (tt >= NL ? NL - 1 : tt);
        s += Xb[(size_t)tt * ND];
    }
    float v = X[e] - s * (1.f / 25.f);
    if (Of) Of[e] = v;
    if (Oh){
        __nv_bfloat16 h = __float2bfloat16(v);
        Oh[e] = h;
        Ol[e] = __float2bfloat16(v - __bfloat162float(h));
    }
}

// ------------------------------- host side -----------------------------------
#define GETSYM(var, sym) do{ cudaGetSymbolAddress((void**)&var, sym); }while(0)

extern "C" void kernel_launch(void* const* d_in, const int* in_sizes, int n_in,
                              void* d_out, int out_size)
{
    const float* x_s      = (const float*)d_in[0];
    const float* x_w      = (const float*)d_in[1];
    const float* wc1_W    = (const float*)d_in[2];
    const float* wc1_b    = (const float*)d_in[3];
    const float* wc2_W    = (const float*)d_in[4];
    const float* wc2_b    = (const float*)d_in[5];
    const float* attn_W   = (const float*)d_in[6];
    const float* attn_b   = (const float*)d_in[7];
    const float* wc1_proj = (const float*)d_in[8];
    const float* wc2_proj = (const float*)d_in[9];
    const float* conv1_W  = (const float*)d_in[10];
    const float* conv2_W  = (const float*)d_in[11];
    float* out  = (float*)d_out;
    float* out2 = out + NBLD;

    float *pv, *pxs, *pxs2, *ptmp, *pmean;
    GETSYM(pv, g_v); GETSYM(pxs, g_xs); GETSYM(pxs2, g_xs2);
    GETSYM(ptmp, g_tmp); GETSYM(pmean, g_mean);
    __nv_bfloat16 *wh, *wl;
    GETSYM(wh, g_wh); GETSYM(wl, g_wl);
    __nv_bfloat16 *phXW,*plXW,*phXSI,*plXSI,*phXW1,*plXW1,*phQ,*plQ,*phK,*plK,
                  *phO,*plO,*phXS,*plXS,*phXS2,*plXS2,*phXSB,*plXSB,*phH,*plH;
    GETSYM(phXW, hXW);  GETSYM(plXW, lXW);
    GETSYM(phXSI,hXSI); GETSYM(plXSI,lXSI);
    GETSYM(phXW1,hXW1); GETSYM(plXW1,lXW1);
    GETSYM(phQ, hQ);    GETSYM(plQ, lQ);
    GETSYM(phK, hK);    GETSYM(plK, lK);
    GETSYM(phO, hO);    GETSYM(plO, lO);
    GETSYM(phXS, hXS);  GETSYM(plXS, lXS);
    GETSYM(phXS2,hXS2); GETSYM(plXS2,lXS2);
    GETSYM(phXSB,hXSB); GETSYM(plXSB,lXSB);
    GETSYM(phH, hH);    GETSYM(plH, lH);

    cudaFuncSetAttribute(gemm_bf, cudaFuncAttributeMaxDynamicSharedMemorySize, SMEM_SZ);
    cudaFuncSetAttribute(corr_bf, cudaFuncAttributeMaxDynamicSharedMemorySize, SMEM_SZ);

    const int nEB = (NBLD + 255) / 256;
    dim3 corrG(12, 12, NB);

    auto G = [&](const __nv_bfloat16* Ah, const __nv_bfloat16* Al, int woff,
                 const float* bias, const float* R, float* Cf,
                 __nv_bfloat16* Ch, __nv_bfloat16* Cl, int N, int K, int shift, int relu){
        dim3 g(N >> 7, 192);
        gemm_bf<<<g, 256, SMEM_SZ>>>(Ah, Al, wh + (size_t)woff * DDW, wl + (size_t)woff * DDW,
                                     bias, R, Cf, Ch, Cl, N, K, shift, relu);
    };

    // ---- weight + input conversions ----------------------------------------
    cvt_kernel<<<(4*DDW/4+255)/256,256>>>(wc1_W,  wh + 0*(size_t)DDW, wl + 0*(size_t)DDW, 4*DDW/4);
    cvt_kernel<<<(4*DDW/4+255)/256,256>>>(attn_W, wh + 4*(size_t)DDW, wl + 4*(size_t)DDW, 4*DDW/4);
    cvt_kernel<<<(4*DDW/4+255)/256,256>>>(wc2_W,  wh + 8*(size_t)DDW, wl + 8*(size_t)DDW, 4*DDW/4);
    cvt_kernel<<<(4*DDW/4+255)/256,256>>>(conv1_W,wh +12*(size_t)DDW, wl +12*(size_t)DDW, 4*DDW/4);
    cvt_kernel<<<(4*DDW/4+255)/256,256>>>(conv2_W,wh +16*(size_t)DDW, wl +16*(size_t)DDW, 4*DDW/4);
    for (int j = 0; j < 3; j++){
        cvt_proj_kernel<<<(DDW+255)/256,256>>>(wc1_proj + j, wh + (20+j)*(size_t)DDW, wl + (20+j)*(size_t)DDW);
        cvt_proj_kernel<<<(DDW+255)/256,256>>>(wc2_proj + j, wh + (23+j)*(size_t)DDW, wl + (23+j)*(size_t)DDW);
    }
    cvt_kernel<<<(NBLD/4+255)/256,256>>>(x_w, phXW,  plXW,  NBLD/4);
    cvt_kernel<<<(NBLD/4+255)/256,256>>>(x_s, phXSI, plXSI, NBLD/4);

    // ---- stage A: x_s += attn(q=x_w, k=v=x_s, wc1) --------------------------
    G(phXW,  plXW,  0, wc1_b,        nullptr, nullptr, phQ, plQ, ND, ND, 0, 0);
    G(phXSI, plXSI, 1, wc1_b + ND,   nullptr, nullptr, phK, plK, ND, ND, 0, 0);
    G(phXSI, plXSI, 2, wc1_b + 2*ND, nullptr, pv,      nullptr, nullptr, ND, ND, 0, 0);
    cudaMemsetAsync(pmean, 0, NB*NL*sizeof(float), 0);
    corr_bf<<<corrG, 256, SMEM_SZ>>>(phQ, plQ, phK, plK);
    topk_kernel<<<1, 512>>>();
    roll_kernel<<<nEB, 256>>>(pv, phO, plO);
    G(phO, plO, 3, wc1_b + 3*ND, x_s, pxs, phXS, plXS, ND, ND, 0, 0);

    // ---- stage B: xw1 = token_embed(x_w, wc1_proj) --------------------------
    G(phXW, plXW, 20, nullptr, nullptr, pxs2, nullptr, nullptr, ND, ND, -1, 0);
    G(phXW, plXW, 21, nullptr, pxs2,    pxs2, nullptr, nullptr, ND, ND,  0, 0);
    G(phXW, plXW, 22, nullptr, pxs2,    nullptr, phXW1, plXW1,  ND, ND,  1, 0);

    // ---- stage C: xs += attn(xs, xs, xs, attn_W) ----------------------------
    G(phXS, plXS, 4, attn_b,        nullptr, nullptr, phQ, plQ, ND, ND, 0, 0);
    G(phXS, plXS, 5, attn_b + ND,   nullptr, nullptr, phK, plK, ND, ND, 0, 0);
    G(phXS, plXS, 6, attn_b + 2*ND, nullptr, pv,      nullptr, nullptr, ND, ND, 0, 0);
    cudaMemsetAsync(pmean, 0, NB*NL*sizeof(float), 0);
    corr_bf<<<corrG, 256, SMEM_SZ>>>(phQ, plQ, phK, plK);
    topk_kernel<<<1, 512>>>();
    roll_kernel<<<nEB, 256>>>(pv, phO, plO);
    G(phO, plO, 7, attn_b + 3*ND, pxs, pxs, nullptr, nullptr, ND, ND, 0, 0);

    // ---- stage D: xs2 = series_decomp(xs) -----------------------------------
    decomp_kernel<<<nEB, 256>>>(pxs, pxs2, phXS2, plXS2);

    // ---- stage E: xs2' = xs2 + attn(q=xw1, k=v=xs2, wc2) --------------------
    G(phXW1, plXW1, 8,  wc2_b,        nullptr, nullptr, phQ, plQ, ND, ND, 0, 0);
    G(phXS2, plXS2, 9,  wc2_b + ND,   nullptr, nullptr, phK, plK, ND, ND, 0, 0);
    G(phXS2, plXS2, 10, wc2_b + 2*ND, nullptr, pv,      nullptr, nullptr, ND, ND, 0, 0);
    cudaMemsetAsync(pmean, 0, NB*NL*sizeof(float), 0);
    corr_bf<<<corrG, 256, SMEM_SZ>>>(phQ, plQ, phK, plK);
    topk_kernel<<<1, 512>>>();
    roll_kernel<<<nEB, 256>>>(pv, phO, plO);
    G(phO, plO, 11, wc2_b + 3*ND, pxs2, ptmp, phXSB, plXSB, ND, ND, 0, 0);

    // ---- stage F: x_w_new = token_embed(xw1, wc2_proj) -> out2 --------------
    G(phXW1, plXW1, 23, nullptr, nullptr, out2, nullptr, nullptr, ND, ND, -1, 0);
    G(phXW1, plXW1, 24, nullptr, out2,    out2, nullptr, nullptr, ND, ND,  0, 0);
    G(phXW1, plXW1, 25, nullptr, out2,    out2, nullptr, nullptr, ND, ND,  1, 0);

    // ---- stage G: FFN + final series_decomp -> out --------------------------
    G(phXSB, plXSB, 12, nullptr, nullptr, nullptr, phH, plH, NDFF, ND,  0, 1);
    G(phH,   plH,   16, nullptr, ptmp,    pv,      nullptr, nullptr, ND, NDFF, 0, 0);
    decomp_kernel<<<nEB, 256>>>(pv, out, nullptr, nullptr);
}

// round 5
// speedup vs baseline: 3.4511x; 1.2540x over previous
#include <cuda_runtime.h>
#include <cuda_bf16.h>
#include <cuda_fp16.h>
#include <cstdint>
#include <math.h>

#define NB    16
#define NL    1536
#define ND    512
#define NDFF  2048
#define NTOPK 7
#define NBLD  (NB*NL*ND)
#define NH    (NB*NL*NDFF)
#define DDW   262144            // 512*512

// ------------------------------- scratch ------------------------------------
__device__ float g_v[NBLD];
__device__ float g_xs[NBLD];
__device__ float g_xs2[NBLD];
__device__ float g_tmp[NBLD];
__device__ float g_mean[NB*NL];
__device__ int   g_idx[NTOPK];
__device__ float g_wt[NB*NTOPK];

// bf16 hi/lo arenas + fp16 q/k
__device__ __nv_bfloat16 g_wh[26*DDW], g_wl[26*DDW];
__device__ __nv_bfloat16 hXW[NBLD],  lXW[NBLD];
__device__ __nv_bfloat16 hXSI[NBLD], lXSI[NBLD];
__device__ __nv_bfloat16 hXW1[NBLD], lXW1[NBLD];
__device__ __nv_bfloat16 hO[NBLD],   lO[NBLD];
__device__ __nv_bfloat16 hXS[NBLD],  lXS[NBLD];
__device__ __nv_bfloat16 hXS2[NBLD], lXS2[NBLD];
__device__ __nv_bfloat16 hXSB[NBLD], lXSB[NBLD];
__device__ __nv_bfloat16 hH[NH],     lH[NH];
__device__ __half        g_fQ[NBLD], g_fK[NBLD];

// ------------------------------- helpers -------------------------------------
__device__ __forceinline__ uint32_t smem_u32(const void* p){
    uint32_t a;
    asm("{ .reg .u64 t; cvta.to.shared.u64 t, %1; cvt.u32.u64 %0, t; }":"=r"(a):"l"(p));
    return a;
}
__device__ __forceinline__ void cp16(uint32_t s, const void* g){
    asm volatile("cp.async.cg.shared.global [%0], [%1], 16;"::"r"(s),"l"(g));
}
__device__ __forceinline__ void cp_commit(){
    asm volatile("cp.async.commit_group;":::"memory");
}
__device__ __forceinline__ void ldm4(uint32_t* r, uint32_t a){
    asm volatile("ldmatrix.sync.aligned.m8n8.x4.shared.b16 {%0,%1,%2,%3}, [%4];"
        : "=r"(r[0]),"=r"(r[1]),"=r"(r[2]),"=r"(r[3]) : "r"(a));
}
__device__ __forceinline__ void mma16816(float* c, const uint32_t* a, uint32_t b0, uint32_t b1){
    asm volatile("mma.sync.aligned.m16n8k16.row.col.f32.bf16.bf16.f32 "
        "{%0,%1,%2,%3},{%4,%5,%6,%7},{%8,%9},{%0,%1,%2,%3};"
        : "+f"(c[0]),"+f"(c[1]),"+f"(c[2]),"+f"(c[3])
        : "r"(a[0]),"r"(a[1]),"r"(a[2]),"r"(a[3]), "r"(b0),"r"(b1));
}
__device__ __forceinline__ void mma16816f(float* c, const uint32_t* a, uint32_t b0, uint32_t b1){
    asm volatile("mma.sync.aligned.m16n8k16.row.col.f32.f16.f16.f32 "
        "{%0,%1,%2,%3},{%4,%5,%6,%7},{%8,%9},{%0,%1,%2,%3};"
        : "+f"(c[0]),"+f"(c[1]),"+f"(c[2]),"+f"(c[3])
        : "r"(a[0]),"r"(a[1]),"r"(a[2]),"r"(a[3]), "r"(b0),"r"(b1));
}
#define SWZ(o) ((o) ^ (((o) >> 3) & 0x70))

#define STG_B   65536u
#define SMEM_SZ (2*STG_B)

// issue one stage of global->smem copies (Ah,Al,Bh,Bl sub-tiles, 128x64 bf16 ea.)
#define LOADC(stage, k0) do{ \
    uint32_t sp_ = sb + (stage)*STG_B; \
    _Pragma("unroll") \
    for (int i_ = 0; i_ < 4; i_++){ \
        cp16(sp_ + soff[i_],          Ah + aoff[i_] + (k0)); \
        cp16(sp_ + 16384 + soff[i_],  Al + aoff[i_] + (k0)); \
        cp16(sp_ + 32768 + soff[i_],  Bh + boff[i_] + (k0)); \
        cp16(sp_ + 49152 + soff[i_],  Bl + boff[i_] + (k0)); \
    } \
    cp_commit(); \
}while(0)

// one 64-wide K chunk of 3-term MMAs (warp tile 64x32)
#define COMPUTE_CHUNK(stg_) do{ \
    uint32_t stg = (stg_)*STG_B; \
    _Pragma("unroll") \
    for (int ks = 0; ks < 4; ks++){ \
        uint32_t ah[4][4], al[4][4], bh[2][4], bl[2][4]; \
        uint32_t ca = ((((ks<<1)|cq) ^ sA) << 4); \
        uint32_t cb = ((((ks<<1)|cq) ^ sB) << 4); \
        _Pragma("unroll") \
        for (int mi = 0; mi < 4; mi++){ \
            uint32_t ad = sb + stg + aB[mi] + ca; \
            ldm4(ah[mi], ad); \
            ldm4(al[mi], ad + 16384); \
        } \
        _Pragma("unroll") \
        for (int nj = 0; nj < 2; nj++){ \
            uint32_t bd = sb + stg + bB[nj] + cb + 32768; \
            ldm4(bh[nj], bd); \
            ldm4(bl[nj], bd + 16384); \
        } \
        _Pragma("unroll") \
        for (int mi = 0; mi < 4; mi++){ \
            _Pragma("unroll") \
            for (int ni = 0; ni < 4; ni++){ \
                uint32_t g = ni >> 1, s = ni & 1; \
                mma16816(acc[mi][ni], ah[mi], bh[g][s], bh[g][s+2]); \
                mma16816(acc[mi][ni], ah[mi], bl[g][s], bl[g][s+2]); \
                mma16816(acc[mi][ni], al[mi], bh[g][s], bh[g][s+2]); \
            } \
        } \
    } \
}while(0)

// warp tiling setup + accumulator init (shared by all mma kernels)
#define WARP_SETUP() \
    int wm = wid >> 2, wn = wid & 3; \
    int rowA = (wm << 6) + (lane & 15); \
    int rowB = (wn << 5) + (lane & 15); \
    uint32_t sA = rowA & 7, sB = rowB & 7, cq = lane >> 4; \
    uint32_t aB[4], bB[2]; \
    _Pragma("unroll") for (int mi = 0; mi < 4; mi++) aB[mi] = (uint32_t)(rowA + (mi<<4)) * 128; \
    _Pragma("unroll") for (int nj = 0; nj < 2; nj++) bB[nj] = (uint32_t)(rowB + (nj<<4)) * 128; \
    float acc[4][4][4]; \
    _Pragma("unroll") for (int mi = 0; mi < 4; mi++) \
        _Pragma("unroll") for (int ni = 0; ni < 4; ni++) \
            _Pragma("unroll") for (int e2 = 0; e2 < 4; e2++) acc[mi][ni][e2] = 0.f;

// epilogue: fragments -> global (bias/R/relu/f32/bf16pair/f16 outputs)
#define EPILOGUE(NN) \
    int gm = m0 + (wm << 6) + (lane >> 2); \
    int gn = n0 + (wn << 5) + ((lane & 3) << 1); \
    _Pragma("unroll") \
    for (int mi = 0; mi < 4; mi++){ \
        _Pragma("unroll") \
        for (int ni = 0; ni < 4; ni++){ \
            _Pragma("unroll") \
            for (int hh = 0; hh < 2; hh++){ \
                int rr = gm + (mi << 4) + hh * 8; \
                int cc = gn + (ni << 3); \
                float v0 = acc[mi][ni][hh*2+0]; \
                float v1 = acc[mi][ni][hh*2+1]; \
                if (bias){ v0 += bias[cc]; v1 += bias[cc+1]; } \
                size_t o = (size_t)rr * (NN) + cc; \
                if (R){ float2 r2 = *reinterpret_cast<const float2*>(R + o); v0 += r2.x; v1 += r2.y; } \
                if (relu){ v0 = fmaxf(v0, 0.f); v1 = fmaxf(v1, 0.f); } \
                if (Cf) *reinterpret_cast<float2*>(Cf + o) = make_float2(v0, v1); \
                if (Cp16){ \
                    *reinterpret_cast<__half2*>(Cp16 + o) = __floats2half2_rn(v0, v1); \
                } \
                if (Ch){ \
                    __nv_bfloat16 h0 = __float2bfloat16(v0), h1 = __float2bfloat16(v1); \
                    *reinterpret_cast<__nv_bfloat162*>(Ch + o) = __nv_bfloat162{h0, h1}; \
                    *reinterpret_cast<__nv_bfloat162*>(Cl + o) = __nv_bfloat162{ \
                        __float2bfloat16(v0 - __bfloat162float(h0)), \
                        __float2bfloat16(v1 - __bfloat162float(h1))}; \
                } \
            } \
        } \
    }

// ------------------------------- GEMM kernel ---------------------------------
// C[m,n] = act( sum_k A[m,k]*W[n,k] + bias[n] + R[m,n] ); A,W bf16 hi/lo pairs.
__global__ void __launch_bounds__(256,1)
gemm_bf(const __nv_bfloat16* __restrict__ Ah, const __nv_bfloat16* __restrict__ Al,
        const __nv_bfloat16* __restrict__ Bh, const __nv_bfloat16* __restrict__ Bl,
        const float* __restrict__ bias, const float* __restrict__ R,
        float* Cf, __nv_bfloat16* Ch, __nv_bfloat16* Cl, __half* Cp16,
        int N, int K, int relu)
{
    extern __shared__ char smem[];
    uint32_t sb = smem_u32(smem);
    int tid = threadIdx.x, wid = tid >> 5, lane = tid & 31;
    int m0 = blockIdx.y << 7, n0 = blockIdx.x << 7;

    size_t aoff[4], boff[4];
    uint32_t soff[4];
    #pragma unroll
    for (int i = 0; i < 4; i++){
        int idx = tid + (i << 8);
        int r = idx >> 3, u = idx & 7;
        aoff[i] = (size_t)(m0 + r) * K + u * 8;
        boff[i] = (size_t)(n0 + r) * K + u * 8;
        soff[i] = SWZ((uint32_t)(r * 128 + u * 16));
    }
    WARP_SETUP();

    int nch = K >> 6;
    LOADC(0, 0);
    for (int c = 0; c < nch; c++){
        if (c + 1 < nch){
            LOADC((c+1)&1, (size_t)(c+1) << 6);
            asm volatile("cp.async.wait_group 1;":::"memory");
        } else {
            asm volatile("cp.async.wait_group 0;":::"memory");
        }
        __syncthreads();
        COMPUTE_CHUNK(c & 1);
        __syncthreads();
    }
    EPILOGUE(N);
}

// --------------------------- fused token-embed -------------------------------
// C[m,n] = sum_tap sum_k A[shift(m,tap-1),k]*Wtap[n,k]; 24 chunks over 3 taps.
__global__ void __launch_bounds__(256,1)
embed_bf(const __nv_bfloat16* __restrict__ Ah, const __nv_bfloat16* __restrict__ Al,
         const __nv_bfloat16* __restrict__ Bh, const __nv_bfloat16* __restrict__ Bl,
         float* Cf, __nv_bfloat16* Ch, __nv_bfloat16* Cl)
{
    extern __shared__ char smem[];
    uint32_t sb = smem_u32(smem);
    int tid = threadIdx.x, wid = tid >> 5, lane = tid & 31;
    int m0 = blockIdx.y << 7, n0 = blockIdx.x << 7;
    const float* bias = nullptr; const float* R = nullptr;
    __half* Cp16 = nullptr; int relu = 0;

    size_t aoff0[4], boff[4];
    int dm1[4], dp1[4];
    uint32_t soff[4];
    #pragma unroll
    for (int i = 0; i < 4; i++){
        int idx = tid + (i << 8);
        int r = idx >> 3, u = idx & 7;
        int am = m0 + r;
        int b = am / NL;
        int t = am - b * NL;
        aoff0[i] = (size_t)am * ND + u * 8;
        dm1[i] = ((t == 0    ? NL - 1 : t - 1) - t) * ND;
        dp1[i] = ((t == NL-1 ? 0      : t + 1) - t) * ND;
        boff[i] = (size_t)(n0 + r) * ND + u * 8;
        soff[i] = SWZ((uint32_t)(r * 128 + u * 16));
    }
    WARP_SETUP();

    #define ELOAD(stage, c_) do{ \
        int tap_ = (c_) >> 3; \
        int kb_ = ((c_) & 7) << 6; \
        size_t bo_ = (size_t)tap_ * DDW + kb_; \
        uint32_t sp_ = sb + (stage)*STG_B; \
        _Pragma("unroll") \
        for (int i_ = 0; i_ < 4; i_++){ \
            long ao_ = (long)aoff0[i_] + (tap_ == 0 ? dm1[i_] : (tap_ == 2 ? dp1[i_] : 0)) + kb_; \
            cp16(sp_ + soff[i_],          Ah + ao_); \
            cp16(sp_ + 16384 + soff[i_],  Al + ao_); \
            cp16(sp_ + 32768 + soff[i_],  Bh + boff[i_] + bo_); \
            cp16(sp_ + 49152 + soff[i_],  Bl + boff[i_] + bo_); \
        } \
        cp_commit(); \
    }while(0)

    ELOAD(0, 0);
    for (int c = 0; c < 24; c++){
        if (c + 1 < 24){
            ELOAD((c+1)&1, c+1);
            asm volatile("cp.async.wait_group 1;":::"memory");
        } else {
            asm volatile("cp.async.wait_group 0;":::"memory");
        }
        __syncthreads();
        COMPUTE_CHUNK(c & 1);
        __syncthreads();
    }
    EPILOGUE(ND);
    #undef ELOAD
}

// --------------------------- correlation (fp16, 1-term) ----------------------
// per batch b: g_mean[b,tau] += (1/512)*sum over (t,s): (t-s)%L==tau of <Q_t,K_s>
#define CSTG_B 32768u
__global__ void __launch_bounds__(256,2)
corr_f16(const __half* __restrict__ Qf, const __half* __restrict__ Kf)
{
    extern __shared__ char smem[];
    uint32_t sb = smem_u32(smem);
    int tid = threadIdx.x, wid = tid >> 5, lane = tid & 31;
    int bb = blockIdx.z;
    size_t base = (size_t)bb * NL * ND;
    int m0 = blockIdx.y << 7, n0 = blockIdx.x << 7;

    size_t aoff[4], boff[4];
    uint32_t soff[4];
    #pragma unroll
    for (int i = 0; i < 4; i++){
        int idx = tid + (i << 8);
        int r = idx >> 3, u = idx & 7;
        aoff[i] = base + (size_t)(m0 + r) * ND + u * 8;
        boff[i] = base + (size_t)(n0 + r) * ND + u * 8;
        soff[i] = SWZ((uint32_t)(r * 128 + u * 16));
    }
    WARP_SETUP();

    #define CLOAD(stage, k0) do{ \
        uint32_t sp_ = sb + (stage)*CSTG_B; \
        _Pragma("unroll") \
        for (int i_ = 0; i_ < 4; i_++){ \
            cp16(sp_ + soff[i_],          Qf + aoff[i_] + (k0)); \
            cp16(sp_ + 16384 + soff[i_],  Kf + boff[i_] + (k0)); \
        } \
        cp_commit(); \
    }while(0)

    CLOAD(0, 0);
    for (int c = 0; c < 8; c++){
        if (c + 1 < 8){
            CLOAD((c+1)&1, (size_t)(c+1) << 6);
            asm volatile("cp.async.wait_group 1;":::"memory");
        } else {
            asm volatile("cp.async.wait_group 0;":::"memory");
        }
        __syncthreads();
        {
            uint32_t stg = (c & 1)*CSTG_B;
            #pragma unroll
            for (int ks = 0; ks < 4; ks++){
                uint32_t ah[4][4], bh[2][4];
                uint32_t ca = ((((ks<<1)|cq) ^ sA) << 4);
                uint32_t cb = ((((ks<<1)|cq) ^ sB) << 4);
                #pragma unroll
                for (int mi = 0; mi < 4; mi++) ldm4(ah[mi], sb + stg + aB[mi] + ca);
                #pragma unroll
                for (int nj = 0; nj < 2; nj++) ldm4(bh[nj], sb + stg + bB[nj] + cb + 16384);
                #pragma unroll
                for (int mi = 0; mi < 4; mi++)
                    #pragma unroll
                    for (int ni = 0; ni < 4; ni++){
                        uint32_t g = ni >> 1, s = ni & 1;
                        mma16816f(acc[mi][ni], ah[mi], bh[g][s], bh[g][s+2]);
                    }
            }
        }
        __syncthreads();
    }
    #undef CLOAD

    // ---- epilogue: anti-diagonal reduction ----------------------------------
    float* bins = reinterpret_cast<float*>(smem);
    if (tid < 255) bins[tid] = 0.f;
    __syncthreads();

    int lm = (wm << 6) + (lane >> 2);
    int ln = (wn << 5) + ((lane & 3) << 1);
    #pragma unroll
    for (int mi = 0; mi < 4; mi++){
        #pragma unroll
        for (int ni = 0; ni < 4; ni++){
            #pragma unroll
            for (int hh = 0; hh < 2; hh++){
                int rr = lm + (mi << 4) + hh * 8;
                int cc = ln + (ni << 3);
                atomicAdd(&bins[rr - cc + 127],     acc[mi][ni][hh*2+0]);
                atomicAdd(&bins[rr - cc - 1 + 127], acc[mi][ni][hh*2+1]);
            }
        }
    }
    __syncthreads();
    if (tid < 255){
        int tau = m0 - n0 + tid - 127;
        tau %= NL; if (tau < 0) tau += NL;
        atomicAdd(&g_mean[bb * NL + tau], bins[tid] * (1.f / 512.f));
    }
}

// ------------------------------ small kernels --------------------------------
__global__ void cvt_kernel(const float* __restrict__ x, __nv_bfloat16* __restrict__ h,
                           __nv_bfloat16* __restrict__ l, int n4)
{
    int i = blockIdx.x * blockDim.x + threadIdx.x;
    if (i >= n4) return;
    float4 v = reinterpret_cast<const float4*>(x)[i];
    __nv_bfloat16 h0=__float2bfloat16(v.x), h1=__float2bfloat16(v.y),
                  h2=__float2bfloat16(v.z), h3=__float2bfloat16(v.w);
    __nv_bfloat162* hp = reinterpret_cast<__nv_bfloat162*>(h);
    __nv_bfloat162* lp = reinterpret_cast<__nv_bfloat162*>(l);
    hp[2*i]   = __nv_bfloat162{h0, h1};
    hp[2*i+1] = __nv_bfloat162{h2, h3};
    lp[2*i]   = __nv_bfloat162{__float2bfloat16(v.x - __bfloat162float(h0)),
                               __float2bfloat16(v.y - __bfloat162float(h1))};
    lp[2*i+1] = __nv_bfloat162{__float2bfloat16(v.z - __bfloat162float(h2)),
                               __float2bfloat16(v.w - __bfloat162float(h3))};
}

// de-stride token-embed weights: dst[n*512+k] = src[n*1536 + k*3]
__global__ void cvt_proj_kernel(const float* __restrict__ src,
                                __nv_bfloat16* __restrict__ h, __nv_bfloat16* __restrict__ l)
{
    int e = blockIdx.x * blockDim.x + threadIdx.x;
    if (e >= DDW) return;
    int n = e >> 9, k = e & 511;
    float v = src[n * 1536 + k * 3];
    __nv_bfloat16 hh = __float2bfloat16(v);
    h[e] = hh;
    l[e] = __float2bfloat16(v - __bfloat162float(hh));
}

__global__ void topk_kernel()
{
    __shared__ float gv[NL];
    __shared__ float rv[512];
    __shared__ int   ri[512];
    __shared__ int   sidx[NTOPK];
    int tid = threadIdx.x;
    for (int t = tid; t < NL; t += 512) {
        float s = 0.f;
        for (int b = 0; b < NB; b++) s += g_mean[b * NL + t];
        gv[t] = s;
    }
    __syncthreads();
    for (int it = 0; it < NTOPK; it++) {
        float bv = -INFINITY; int bi = 0x7fffffff;
        for (int t = tid; t < NL; t += 512) {
            float v = gv[t];
            if (v > bv || (v == bv && t < bi)) { bv = v; bi = t; }
        }
        rv[tid] = bv; ri[tid] = bi;
        __syncthreads();
        for (int s = 256; s > 0; s >>= 1) {
            if (tid < s) {
                if (rv[tid+s] > rv[tid] || (rv[tid+s] == rv[tid] && ri[tid+s] < ri[tid])) {
                    rv[tid] = rv[tid+s]; ri[tid] = ri[tid+s];
                }
            }
            __syncthreads();
        }
        if (tid == 0) { sidx[it] = ri[0]; gv[ri[0]] = -INFINITY; }
        __syncthreads();
    }
    if (tid < NTOPK) g_idx[tid] = sidx[tid];
    if (tid < NB) {
        float vals[NTOPK];
        float mx = -INFINITY;
        for (int i = 0; i < NTOPK; i++) {
            vals[i] = g_mean[tid * NL + sidx[i]];
            mx = fmaxf(mx, vals[i]);
        }
        float s = 0.f;
        for (int i = 0; i < NTOPK; i++) { vals[i] = expf(vals[i] - mx); s += vals[i]; }
        float inv = 1.f / s;
        for (int i = 0; i < NTOPK; i++) g_wt[tid * NTOPK + i] = vals[i] * inv;
    }
}

__global__ void roll_kernel(const float* __restrict__ V,
                            __nv_bfloat16* __restrict__ Oh, __nv_bfloat16* __restrict__ Ol)
{
    size_t e = (size_t)blockIdx.x * blockDim.x + threadIdx.x;
    if (e >= (size_t)NBLD) return;
    int d = (int)(e & (ND - 1));
    size_t row = e >> 9;
    int b = (int)(row / NL);
    int t = (int)(row - (size_t)b * NL);
    float s = 0.f;
    #pragma unroll
    for (int i = 0; i < NTOPK; i++) {
        int tt = t + g_idx[i];
        if (tt >= NL) tt -= NL;
        s += g_wt[b * NTOPK + i] * V[((size_t)b * NL + tt) * ND + d];
    }
    __nv_bfloat16 h = __float2bfloat16(s);
    Oh[e] = h;
    Ol[e] = __float2bfloat16(s - __bfloat162float(h));
}

__global__ void decomp_kernel(const float* __restrict__ X, float* __restrict__ Of,
                              __nv_bfloat16* Oh, __nv_bfloat16* Ol)
{
    size_t e = (size_t)blockIdx.x * blockDim.x + threadIdx.x;
    if (e >= (size_t)NBLD) return;
    int d = (int)(e & (ND - 1));
    size_t row = e >> 9;
    int b = (int)(row / NL);
    int t = (int)(row - (size_t)b * NL);
    const float* Xb = X + (size_t)b * NL * ND + d;
    float s = 0.f;
    #pragma unroll
    for (int u = -12; u <= 12; u++) {
        int tt = t + u;
        tt = tt < 0 ? 0 : (tt >= NL ? NL - 1 : tt);
        s += Xb[(size_t)tt * ND];
    }
    float v = X[e] - s * (1.f / 25.f);
    if (Of) Of[e] = v;
    if (Oh){
        __nv_bfloat16 h = __float2bfloat16(v);
        Oh[e] = h;
        Ol[e] = __float2bfloat16(v - __bfloat162float(h));
    }
}

// ------------------------------- host side -----------------------------------
#define GETSYM(var, sym) do{ cudaGetSymbolAddress((void**)&var, sym); }while(0)

extern "C" void kernel_launch(void* const* d_in, const int* in_sizes, int n_in,
                              void* d_out, int out_size)
{
    const float* x_s      = (const float*)d_in[0];
    const float* x_w      = (const float*)d_in[1];
    const float* wc1_W    = (const float*)d_in[2];
    const float* wc1_b    = (const float*)d_in[3];
    const float* wc2_W    = (const float*)d_in[4];
    const float* wc2_b    = (const float*)d_in[5];
    const float* attn_W   = (const float*)d_in[6];
    const float* attn_b   = (const float*)d_in[7];
    const float* wc1_proj = (const float*)d_in[8];
    const float* wc2_proj = (const float*)d_in[9];
    const float* conv1_W  = (const float*)d_in[10];
    const float* conv2_W  = (const float*)d_in[11];
    float* out  = (float*)d_out;
    float* out2 = out + NBLD;

    float *pv, *pxs, *pxs2, *ptmp, *pmean;
    GETSYM(pv, g_v); GETSYM(pxs, g_xs); GETSYM(pxs2, g_xs2);
    GETSYM(ptmp, g_tmp); GETSYM(pmean, g_mean);
    __nv_bfloat16 *wh, *wl;
    GETSYM(wh, g_wh); GETSYM(wl, g_wl);
    __nv_bfloat16 *phXW,*plXW,*phXSI,*plXSI,*phXW1,*plXW1,
                  *phO,*plO,*phXS,*plXS,*phXS2,*plXS2,*phXSB,*plXSB,*phH,*plH;
    __half *pfQ, *pfK;
    GETSYM(phXW, hXW);  GETSYM(plXW, lXW);
    GETSYM(phXSI,hXSI); GETSYM(plXSI,lXSI);
    GETSYM(phXW1,hXW1); GETSYM(plXW1,lXW1);
    GETSYM(phO, hO);    GETSYM(plO, lO);
    GETSYM(phXS, hXS);  GETSYM(plXS, lXS);
    GETSYM(phXS2,hXS2); GETSYM(plXS2,lXS2);
    GETSYM(phXSB,hXSB); GETSYM(plXSB,lXSB);
    GETSYM(phH, hH);    GETSYM(plH, lH);
    GETSYM(pfQ, g_fQ);  GETSYM(pfK, g_fK);

    cudaFuncSetAttribute(gemm_bf,  cudaFuncAttributeMaxDynamicSharedMemorySize, SMEM_SZ);
    cudaFuncSetAttribute(embed_bf, cudaFuncAttributeMaxDynamicSharedMemorySize, SMEM_SZ);
    cudaFuncSetAttribute(corr_f16, cudaFuncAttributeMaxDynamicSharedMemorySize, 2*CSTG_B);

    const int nEB = (NBLD + 255) / 256;
    dim3 corrG(12, 12, NB);
    dim3 embG(4, 192);

    auto G = [&](const __nv_bfloat16* Ah, const __nv_bfloat16* Al, int woff,
                 const float* bias, const float* R, float* Cf,
                 __nv_bfloat16* Ch, __nv_bfloat16* Cl, __half* Cp16,
                 int N, int K, int relu){
        dim3 g(N >> 7, 192);
        gemm_bf<<<g, 256, SMEM_SZ>>>(Ah, Al, wh + (size_t)woff * DDW, wl + (size_t)woff * DDW,
                                     bias, R, Cf, Ch, Cl, Cp16, N, K, relu);
    };

    // ---- weight + input conversions ----------------------------------------
    cvt_kernel<<<(4*DDW/4+255)/256,256>>>(wc1_W,  wh + 0*(size_t)DDW, wl + 0*(size_t)DDW, 4*DDW/4);
    cvt_kernel<<<(4*DDW/4+255)/256,256>>>(attn_W, wh + 4*(size_t)DDW, wl + 4*(size_t)DDW, 4*DDW/4);
    cvt_kernel<<<(4*DDW/4+255)/256,256>>>(wc2_W,  wh + 8*(size_t)DDW, wl + 8*(size_t)DDW, 4*DDW/4);
    cvt_kernel<<<(4*DDW/4+255)/256,256>>>(conv1_W,wh +12*(size_t)DDW, wl +12*(size_t)DDW, 4*DDW/4);
    cvt_kernel<<<(4*DDW/4+255)/256,256>>>(conv2_W,wh +16*(size_t)DDW, wl +16*(size_t)DDW, 4*DDW/4);
    for (int j = 0; j < 3; j++){
        cvt_proj_kernel<<<(DDW+255)/256,256>>>(wc1_proj + j, wh + (20+j)*(size_t)DDW, wl + (20+j)*(size_t)DDW);
        cvt_proj_kernel<<<(DDW+255)/256,256>>>(wc2_proj + j, wh + (23+j)*(size_t)DDW, wl + (23+j)*(size_t)DDW);
    }
    cvt_kernel<<<(NBLD/4+255)/256,256>>>(x_w, phXW,  plXW,  NBLD/4);
    cvt_kernel<<<(NBLD/4+255)/256,256>>>(x_s, phXSI, plXSI, NBLD/4);

    // ---- stage A: x_s += attn(q=x_w, k=v=x_s, wc1) --------------------------
    G(phXW,  plXW,  0, wc1_b,        nullptr, nullptr, nullptr, nullptr, pfQ, ND, ND, 0);
    G(phXSI, plXSI, 1, wc1_b + ND,   nullptr, nullptr, nullptr, nullptr, pfK, ND, ND, 0);
    G(phXSI, plXSI, 2, wc1_b + 2*ND, nullptr, pv,      nullptr, nullptr, nullptr, ND, ND, 0);
    cudaMemsetAsync(pmean, 0, NB*NL*sizeof(float), 0);
    corr_f16<<<corrG, 256, 2*CSTG_B>>>(pfQ, pfK);
    topk_kernel<<<1, 512>>>();
    roll_kernel<<<nEB, 256>>>(pv, phO, plO);
    G(phO, plO, 3, wc1_b + 3*ND, x_s, pxs, phXS, plXS, nullptr, ND, ND, 0);

    // ---- stage B: xw1 = token_embed(x_w, wc1_proj)  (fused 3-tap) -----------
    embed_bf<<<embG, 256, SMEM_SZ>>>(phXW, plXW, wh + 20*(size_t)DDW, wl + 20*(size_t)DDW,
                                     nullptr, phXW1, plXW1);

    // ---- stage C: xs += attn(xs, xs, xs, attn_W) ----------------------------
    G(phXS, plXS, 4, attn_b,        nullptr, nullptr, nullptr, nullptr, pfQ, ND, ND, 0);
    G(phXS, plXS, 5, attn_b + ND,   nullptr, nullptr, nullptr, nullptr, pfK, ND, ND, 0);
    G(phXS, plXS, 6, attn_b + 2*ND, nullptr, pv,      nullptr, nullptr, nullptr, ND, ND, 0);
    cudaMemsetAsync(pmean, 0, NB*NL*sizeof(float), 0);
    corr_f16<<<corrG, 256, 2*CSTG_B>>>(pfQ, pfK);
    topk_kernel<<<1, 512>>>();
    roll_kernel<<<nEB, 256>>>(pv, phO, plO);
    G(phO, plO, 7, attn_b + 3*ND, pxs, pxs, nullptr, nullptr, nullptr, ND, ND, 0);

    // ---- stage D: xs2 = series_decomp(xs) -----------------------------------
    decomp_kernel<<<nEB, 256>>>(pxs, pxs2, phXS2, plXS2);

    // ---- stage E: xs2' = xs2 + attn(q=xw1, k=v=xs2, wc2) --------------------
    G(phXW1, plXW1, 8,  wc2_b,        nullptr, nullptr, nullptr, nullptr, pfQ, ND, ND, 0);
    G(phXS2, plXS2, 9,  wc2_b + ND,   nullptr, nullptr, nullptr, nullptr, pfK, ND, ND, 0);
    G(phXS2, plXS2, 10, wc2_b + 2*ND, nullptr, pv,      nullptr, nullptr, nullptr, ND, ND, 0);
    cudaMemsetAsync(pmean, 0, NB*NL*sizeof(float), 0);
    corr_f16<<<corrG, 256, 2*CSTG_B>>>(pfQ, pfK);
    topk_kernel<<<1, 512>>>();
    roll_kernel<<<nEB, 256>>>(pv, phO, plO);
    G(phO, plO, 11, wc2_b + 3*ND, pxs2, ptmp, phXSB, plXSB, nullptr, ND, ND, 0);

    // ---- stage F: x_w_new = token_embed(xw1, wc2_proj) -> out2 (fused) ------
    embed_bf<<<embG, 256, SMEM_SZ>>>(phXW1, plXW1, wh + 23*(size_t)DDW, wl + 23*(size_t)DDW,
                                     out2, nullptr, nullptr);

    // ---- stage G: FFN + final series_decomp -> out --------------------------
    G(phXSB, plXSB, 12, nullptr, nullptr, nullptr, phH, plH, nullptr, NDFF, ND,  1);
    G(phH,   plH,   16, nullptr, ptmp,    pv,      nullptr, nullptr, nullptr, ND, NDFF, 0);
    decomp_kernel<<<nEB, 256>>>(pv, out, nullptr, nullptr);
}

// round 6
// speedup vs baseline: 6.0334x; 1.7482x over previous
#include <cuda_runtime.h>
#include <cuda_fp16.h>
#include <cstdint>
#include <math.h>

#define NB    16
#define NL    1536
#define ND    512
#define NDFF  2048
#define NTOPK 7
#define NBLD  (NB*NL*ND)
#define NH    (NB*NL*NDFF)
#define DDW   262144            // 512*512

// ------------------------------- scratch ------------------------------------
__device__ float g_v[NBLD];
__device__ float g_xs[NBLD];
__device__ float g_xs2[NBLD];
__device__ float g_tmp[NBLD];
__device__ float g_mean[NB*NL];
__device__ int   g_idx[NTOPK];
__device__ float g_wt[NB*NTOPK];

// fp16 arenas
__device__ __half g_wf[20*DDW];               // wc1(4) attn(4) wc2(4) conv1(4) conv2(4)
__device__ __half g_weh[6*DDW], g_wel[6*DDW]; // embed weights hi/lo (wc1_proj 0-2, wc2_proj 3-5)
__device__ __half fXWh[NBLD], fXWl[NBLD];
__device__ __half fXSI[NBLD];
__device__ __half fQ[NBLD], fK[NBLD], fO[NBLD];
__device__ __half fXSa[NBLD], fXS2[NBLD];
__device__ __half fXW1h[NBLD], fXW1l[NBLD];
__device__ __half fXSB[NBLD];
__device__ __half fH[NH];

// ------------------------------- helpers -------------------------------------
__device__ __forceinline__ uint32_t smem_u32(const void* p){
    uint32_t a;
    asm("{ .reg .u64 t; cvta.to.shared.u64 t, %1; cvt.u32.u64 %0, t; }":"=r"(a):"l"(p));
    return a;
}
__device__ __forceinline__ void cp16(uint32_t s, const void* g){
    asm volatile("cp.async.cg.shared.global [%0], [%1], 16;"::"r"(s),"l"(g));
}
__device__ __forceinline__ void cp_commit(){
    asm volatile("cp.async.commit_group;":::"memory");
}
__device__ __forceinline__ void ldm4(uint32_t* r, uint32_t a){
    asm volatile("ldmatrix.sync.aligned.m8n8.x4.shared.b16 {%0,%1,%2,%3}, [%4];"
        : "=r"(r[0]),"=r"(r[1]),"=r"(r[2]),"=r"(r[3]) : "r"(a));
}
__device__ __forceinline__ void mma16816f(float* c, const uint32_t* a, uint32_t b0, uint32_t b1){
    asm volatile("mma.sync.aligned.m16n8k16.row.col.f32.f16.f16.f32 "
        "{%0,%1,%2,%3},{%4,%5,%6,%7},{%8,%9},{%0,%1,%2,%3};"
        : "+f"(c[0]),"+f"(c[1]),"+f"(c[2]),"+f"(c[3])
        : "r"(a[0]),"r"(a[1]),"r"(a[2]),"r"(a[3]), "r"(b0),"r"(b1));
}
#define SWZ(o) ((o) ^ (((o) >> 3) & 0x70))
#define SSTG 32768u

// warp tiling setup + accumulator init
#define WARP_SETUP() \
    int wm = wid >> 2, wn = wid & 3; \
    int rowA = (wm << 6) + (lane & 15); \
    int rowB = (wn << 5) + (lane & 15); \
    uint32_t sA = rowA & 7, sB = rowB & 7, cq = lane >> 4; \
    uint32_t aB[4], bB[2]; \
    _Pragma("unroll") for (int mi = 0; mi < 4; mi++) aB[mi] = (uint32_t)(rowA + (mi<<4)) * 128; \
    _Pragma("unroll") for (int nj = 0; nj < 2; nj++) bB[nj] = (uint32_t)(rowB + (nj<<4)) * 128; \
    float acc[4][4][4]; \
    _Pragma("unroll") for (int mi = 0; mi < 4; mi++) \
        _Pragma("unroll") for (int ni = 0; ni < 4; ni++) \
            _Pragma("unroll") for (int e2 = 0; e2 < 4; e2++) acc[mi][ni][e2] = 0.f;

// ------------------------------- single-term fp16 GEMM -----------------------
// C[m,n] = act( sum_k A[m,k]*W[n,k] + bias[n] + R[m,n] )
__global__ void __launch_bounds__(256,2)
gemm_s(const __half* __restrict__ A, const __half* __restrict__ W,
       const float* __restrict__ bias, const float* __restrict__ R,
       float* Cf, __half* C16, int N, int K, int relu)
{
    extern __shared__ char smem[];
    uint32_t sb = smem_u32(smem);
    int tid = threadIdx.x, wid = tid >> 5, lane = tid & 31;
    int m0 = blockIdx.y << 7, n0 = blockIdx.x << 7;

    size_t aoff[4], boff[4];
    uint32_t soff[4];
    #pragma unroll
    for (int i = 0; i < 4; i++){
        int idx = tid + (i << 8);
        int r = idx >> 3, u = idx & 7;
        aoff[i] = (size_t)(m0 + r) * K + u * 8;
        boff[i] = (size_t)(n0 + r) * K + u * 8;
        soff[i] = SWZ((uint32_t)(r * 128 + u * 16));
    }
    WARP_SETUP();

    int nch = K >> 6;
    {
        uint32_t sp_ = sb;
        #pragma unroll
        for (int i = 0; i < 4; i++){
            cp16(sp_ + soff[i],         A + aoff[i]);
            cp16(sp_ + 16384 + soff[i], W + boff[i]);
        }
        cp_commit();
    }
    for (int c = 0; c < nch; c++){
        if (c + 1 < nch){
            uint32_t sp_ = sb + ((c+1)&1)*SSTG;
            size_t k0 = (size_t)(c+1) << 6;
            #pragma unroll
            for (int i = 0; i < 4; i++){
                cp16(sp_ + soff[i],         A + aoff[i] + k0);
                cp16(sp_ + 16384 + soff[i], W + boff[i] + k0);
            }
            cp_commit();
            asm volatile("cp.async.wait_group 1;":::"memory");
        } else {
            asm volatile("cp.async.wait_group 0;":::"memory");
        }
        __syncthreads();
        {
            uint32_t stg = (c & 1)*SSTG;
            #pragma unroll
            for (int ks = 0; ks < 4; ks++){
                uint32_t ah[4][4], bh[2][4];
                uint32_t ca = ((((ks<<1)|cq) ^ sA) << 4);
                uint32_t cb = ((((ks<<1)|cq) ^ sB) << 4);
                #pragma unroll
                for (int mi = 0; mi < 4; mi++) ldm4(ah[mi], sb + stg + aB[mi] + ca);
                #pragma unroll
                for (int nj = 0; nj < 2; nj++) ldm4(bh[nj], sb + stg + bB[nj] + cb + 16384);
                #pragma unroll
                for (int mi = 0; mi < 4; mi++)
                    #pragma unroll
                    for (int ni = 0; ni < 4; ni++){
                        uint32_t g = ni >> 1, s = ni & 1;
                        mma16816f(acc[mi][ni], ah[mi], bh[g][s], bh[g][s+2]);
                    }
            }
        }
        __syncthreads();
    }

    int gm = m0 + (wm << 6) + (lane >> 2);
    int gn = n0 + (wn << 5) + ((lane & 3) << 1);
    #pragma unroll
    for (int mi = 0; mi < 4; mi++)
        #pragma unroll
        for (int ni = 0; ni < 4; ni++)
            #pragma unroll
            for (int hh = 0; hh < 2; hh++){
                int rr = gm + (mi << 4) + hh * 8;
                int cc = gn + (ni << 3);
                float v0 = acc[mi][ni][hh*2+0];
                float v1 = acc[mi][ni][hh*2+1];
                if (bias){ v0 += bias[cc]; v1 += bias[cc+1]; }
                size_t o = (size_t)rr * N + cc;
                if (R){ float2 r2 = *reinterpret_cast<const float2*>(R + o); v0 += r2.x; v1 += r2.y; }
                if (relu){ v0 = fmaxf(v0, 0.f); v1 = fmaxf(v1, 0.f); }
                if (Cf)  *reinterpret_cast<float2*>(Cf + o)  = make_float2(v0, v1);
                if (C16) *reinterpret_cast<__half2*>(C16 + o) = __floats2half2_rn(v0, v1);
            }
}

// --------------------------- fused token-embed (templated terms) -------------
// C[m,n] = sum_tap sum_k A[shift(m,tap-1),k]*Wtap[n,k]; 24 chunks over 3 taps.
template<int TERMS>
__global__ void __launch_bounds__(256, TERMS==1?2:1)
embed_f16(const __half* __restrict__ Ah, const __half* __restrict__ Al,
          const __half* __restrict__ Bh, const __half* __restrict__ Bl,
          float* Cf, __half* Ch, __half* Cl)
{
    constexpr uint32_t STG = (TERMS == 3) ? 65536u : 32768u;
    constexpr uint32_t BO  = (TERMS == 3) ? 32768u : 16384u;
    extern __shared__ char smem[];
    uint32_t sb = smem_u32(smem);
    int tid = threadIdx.x, wid = tid >> 5, lane = tid & 31;
    int m0 = blockIdx.y << 7, n0 = blockIdx.x << 7;

    size_t aoff0[4], boff[4];
    int dm1[4], dp1[4];
    uint32_t soff[4];
    #pragma unroll
    for (int i = 0; i < 4; i++){
        int idx = tid + (i << 8);
        int r = idx >> 3, u = idx & 7;
        int am = m0 + r;
        int b = am / NL;
        int t = am - b * NL;
        aoff0[i] = (size_t)am * ND + u * 8;
        dm1[i] = ((t == 0    ? NL - 1 : t - 1) - t) * ND;
        dp1[i] = ((t == NL-1 ? 0      : t + 1) - t) * ND;
        boff[i] = (size_t)(n0 + r) * ND + u * 8;
        soff[i] = SWZ((uint32_t)(r * 128 + u * 16));
    }
    WARP_SETUP();

    #define ELOAD(stage, c_) do{ \
        int tap_ = (c_) >> 3; \
        int kb_ = ((c_) & 7) << 6; \
        size_t bo_ = (size_t)tap_ * DDW + kb_; \
        uint32_t sp_ = sb + (stage)*STG; \
        _Pragma("unroll") \
        for (int i_ = 0; i_ < 4; i_++){ \
            long ao_ = (long)aoff0[i_] + (tap_ == 0 ? dm1[i_] : (tap_ == 2 ? dp1[i_] : 0)) + kb_; \
            cp16(sp_ + soff[i_],      Ah + ao_); \
            if (TERMS == 3) cp16(sp_ + 16384 + soff[i_], Al + ao_); \
            cp16(sp_ + BO + soff[i_], Bh + boff[i_] + bo_); \
            if (TERMS == 3) cp16(sp_ + BO + 16384 + soff[i_], Bl + boff[i_] + bo_); \
        } \
        cp_commit(); \
    }while(0)

    ELOAD(0, 0);
    for (int c = 0; c < 24; c++){
        if (c + 1 < 24){
            ELOAD((c+1)&1, c+1);
            asm volatile("cp.async.wait_group 1;":::"memory");
        } else {
            asm volatile("cp.async.wait_group 0;":::"memory");
        }
        __syncthreads();
        {
            uint32_t stg = (c & 1)*STG;
            #pragma unroll
            for (int ks = 0; ks < 4; ks++){
                uint32_t ah[4][4], al[4][4], bh[2][4], bl[2][4];
                uint32_t ca = ((((ks<<1)|cq) ^ sA) << 4);
                uint32_t cb = ((((ks<<1)|cq) ^ sB) << 4);
                #pragma unroll
                for (int mi = 0; mi < 4; mi++){
                    uint32_t ad = sb + stg + aB[mi] + ca;
                    ldm4(ah[mi], ad);
                    if (TERMS == 3) ldm4(al[mi], ad + 16384);
                }
                #pragma unroll
                for (int nj = 0; nj < 2; nj++){
                    uint32_t bd = sb + stg + bB[nj] + cb + BO;
                    ldm4(bh[nj], bd);
                    if (TERMS == 3) ldm4(bl[nj], bd + 16384);
                }
                #pragma unroll
                for (int mi = 0; mi < 4; mi++)
                    #pragma unroll
                    for (int ni = 0; ni < 4; ni++){
                        uint32_t g = ni >> 1, s = ni & 1;
                        mma16816f(acc[mi][ni], ah[mi], bh[g][s], bh[g][s+2]);
                        if (TERMS == 3){
                            mma16816f(acc[mi][ni], ah[mi], bl[g][s], bl[g][s+2]);
                            mma16816f(acc[mi][ni], al[mi], bh[g][s], bh[g][s+2]);
                        }
                    }
            }
        }
        __syncthreads();
    }
    #undef ELOAD

    int gm = m0 + (wm << 6) + (lane >> 2);
    int gn = n0 + (wn << 5) + ((lane & 3) << 1);
    #pragma unroll
    for (int mi = 0; mi < 4; mi++)
        #pragma unroll
        for (int ni = 0; ni < 4; ni++)
            #pragma unroll
            for (int hh = 0; hh < 2; hh++){
                int rr = gm + (mi << 4) + hh * 8;
                int cc = gn + (ni << 3);
                float v0 = acc[mi][ni][hh*2+0];
                float v1 = acc[mi][ni][hh*2+1];
                size_t o = (size_t)rr * ND + cc;
                if (Cf) *reinterpret_cast<float2*>(Cf + o) = make_float2(v0, v1);
                if (Ch){
                    __half h0 = __float2half_rn(v0), h1 = __float2half_rn(v1);
                    *reinterpret_cast<__half2*>(Ch + o) = __half2{h0, h1};
                    *reinterpret_cast<__half2*>(Cl + o) = __half2{
                        __float2half_rn(v0 - __half2float(h0)),
                        __float2half_rn(v1 - __half2float(h1))};
                }
            }
}

// --------------------------- correlation (fp16, 1-term) ----------------------
__global__ void __launch_bounds__(256,2)
corr_f16(const __half* __restrict__ Qf, const __half* __restrict__ Kf)
{
    extern __shared__ char smem[];
    uint32_t sb = smem_u32(smem);
    int tid = threadIdx.x, wid = tid >> 5, lane = tid & 31;
    int bb = blockIdx.z;
    size_t base = (size_t)bb * NL * ND;
    int m0 = blockIdx.y << 7, n0 = blockIdx.x << 7;

    size_t aoff[4], boff[4];
    uint32_t soff[4];
    #pragma unroll
    for (int i = 0; i < 4; i++){
        int idx = tid + (i << 8);
        int r = idx >> 3, u = idx & 7;
        aoff[i] = base + (size_t)(m0 + r) * ND + u * 8;
        boff[i] = base + (size_t)(n0 + r) * ND + u * 8;
        soff[i] = SWZ((uint32_t)(r * 128 + u * 16));
    }
    WARP_SETUP();

    #define CLOAD(stage, k0) do{ \
        uint32_t sp_ = sb + (stage)*SSTG; \
        _Pragma("unroll") \
        for (int i_ = 0; i_ < 4; i_++){ \
            cp16(sp_ + soff[i_],          Qf + aoff[i_] + (k0)); \
            cp16(sp_ + 16384 + soff[i_],  Kf + boff[i_] + (k0)); \
        } \
        cp_commit(); \
    }while(0)

    CLOAD(0, 0);
    for (int c = 0; c < 8; c++){
        if (c + 1 < 8){
            CLOAD((c+1)&1, (size_t)(c+1) << 6);
            asm volatile("cp.async.wait_group 1;":::"memory");
        } else {
            asm volatile("cp.async.wait_group 0;":::"memory");
        }
        __syncthreads();
        {
            uint32_t stg = (c & 1)*SSTG;
            #pragma unroll
            for (int ks = 0; ks < 4; ks++){
                uint32_t ah[4][4], bh[2][4];
                uint32_t ca = ((((ks<<1)|cq) ^ sA) << 4);
                uint32_t cb = ((((ks<<1)|cq) ^ sB) << 4);
                #pragma unroll
                for (int mi = 0; mi < 4; mi++) ldm4(ah[mi], sb + stg + aB[mi] + ca);
                #pragma unroll
                for (int nj = 0; nj < 2; nj++) ldm4(bh[nj], sb + stg + bB[nj] + cb + 16384);
                #pragma unroll
                for (int mi = 0; mi < 4; mi++)
                    #pragma unroll
                    for (int ni = 0; ni < 4; ni++){
                        uint32_t g = ni >> 1, s = ni & 1;
                        mma16816f(acc[mi][ni], ah[mi], bh[g][s], bh[g][s+2]);
                    }
            }
        }
        __syncthreads();
    }
    #undef CLOAD

    float* bins = reinterpret_cast<float*>(smem);
    if (tid < 255) bins[tid] = 0.f;
    __syncthreads();

    int lm = (wm << 6) + (lane >> 2);
    int ln = (wn << 5) + ((lane & 3) << 1);
    #pragma unroll
    for (int mi = 0; mi < 4; mi++)
        #pragma unroll
        for (int ni = 0; ni < 4; ni++)
            #pragma unroll
            for (int hh = 0; hh < 2; hh++){
                int rr = lm + (mi << 4) + hh * 8;
                int cc = ln + (ni << 3);
                atomicAdd(&bins[rr - cc + 127],     acc[mi][ni][hh*2+0]);
                atomicAdd(&bins[rr - cc - 1 + 127], acc[mi][ni][hh*2+1]);
            }
    __syncthreads();
    if (tid < 255){
        int tau = m0 - n0 + tid - 127;
        tau %= NL; if (tau < 0) tau += NL;
        atomicAdd(&g_mean[bb * NL + tau], bins[tid] * (1.f / 512.f));
    }
}

// ------------------------------ small kernels --------------------------------
__global__ void cvt_f16s(const float* __restrict__ x, __half* __restrict__ o, int n4)
{
    int i = blockIdx.x * blockDim.x + threadIdx.x;
    if (i >= n4) return;
    float4 v = reinterpret_cast<const float4*>(x)[i];
    __half2* op = reinterpret_cast<__half2*>(o);
    op[2*i]   = __floats2half2_rn(v.x, v.y);
    op[2*i+1] = __floats2half2_rn(v.z, v.w);
}

__global__ void cvt_f16hl(const float* __restrict__ x, __half* __restrict__ h,
                          __half* __restrict__ l, int n4)
{
    int i = blockIdx.x * blockDim.x + threadIdx.x;
    if (i >= n4) return;
    float4 v = reinterpret_cast<const float4*>(x)[i];
    __half h0=__float2half_rn(v.x), h1=__float2half_rn(v.y),
           h2=__float2half_rn(v.z), h3=__float2half_rn(v.w);
    __half2* hp = reinterpret_cast<__half2*>(h);
    __half2* lp = reinterpret_cast<__half2*>(l);
    hp[2*i]   = __half2{h0, h1};
    hp[2*i+1] = __half2{h2, h3};
    lp[2*i]   = __half2{__float2half_rn(v.x - __half2float(h0)),
                        __float2half_rn(v.y - __half2float(h1))};
    lp[2*i+1] = __half2{__float2half_rn(v.z - __half2float(h2)),
                        __float2half_rn(v.w - __half2float(h3))};
}

// de-stride token-embed weights: dst[n*512+k] = src[n*1536 + k*3]
__global__ void cvt_proj_f16(const float* __restrict__ src,
                             __half* __restrict__ h, __half* __restrict__ l)
{
    int e = blockIdx.x * blockDim.x + threadIdx.x;
    if (e >= DDW) return;
    int n = e >> 9, k = e & 511;
    float v = src[n * 1536 + k * 3];
    __half hh = __float2half_rn(v);
    h[e] = hh;
    l[e] = __float2half_rn(v - __half2float(hh));
}

__global__ void topk_kernel()
{
    __shared__ float gv[NL];
    __shared__ float rv[512];
    __shared__ int   ri[512];
    __shared__ int   sidx[NTOPK];
    int tid = threadIdx.x;
    for (int t = tid; t < NL; t += 512) {
        float s = 0.f;
        for (int b = 0; b < NB; b++) s += g_mean[b * NL + t];
        gv[t] = s;
    }
    __syncthreads();
    for (int it = 0; it < NTOPK; it++) {
        float bv = -INFINITY; int bi = 0x7fffffff;
        for (int t = tid; t < NL; t += 512) {
            float v = gv[t];
            if (v > bv || (v == bv && t < bi)) { bv = v; bi = t; }
        }
        rv[tid] = bv; ri[tid] = bi;
        __syncthreads();
        for (int s = 256; s > 0; s >>= 1) {
            if (tid < s) {
                if (rv[tid+s] > rv[tid] || (rv[tid+s] == rv[tid] && ri[tid+s] < ri[tid])) {
                    rv[tid] = rv[tid+s]; ri[tid] = ri[tid+s];
                }
            }
            __syncthreads();
        }
        if (tid == 0) { sidx[it] = ri[0]; gv[ri[0]] = -INFINITY; }
        __syncthreads();
    }
    if (tid < NTOPK) g_idx[tid] = sidx[tid];
    if (tid < NB) {
        float vals[NTOPK];
        float mx = -INFINITY;
        for (int i = 0; i < NTOPK; i++) {
            vals[i] = g_mean[tid * NL + sidx[i]];
            mx = fmaxf(mx, vals[i]);
        }
        float s = 0.f;
        for (int i = 0; i < NTOPK; i++) { vals[i] = expf(vals[i] - mx); s += vals[i]; }
        float inv = 1.f / s;
        for (int i = 0; i < NTOPK; i++) g_wt[tid * NTOPK + i] = vals[i] * inv;
    }
}

__global__ void roll_kernel(const float* __restrict__ V, __half* __restrict__ O16)
{
    size_t e = (size_t)blockIdx.x * blockDim.x + threadIdx.x;
    if (e >= (size_t)NBLD) return;
    int d = (int)(e & (ND - 1));
    size_t row = e >> 9;
    int b = (int)(row / NL);
    int t = (int)(row - (size_t)b * NL);
    float s = 0.f;
    #pragma unroll
    for (int i = 0; i < NTOPK; i++) {
        int tt = t + g_idx[i];
        if (tt >= NL) tt -= NL;
        s += g_wt[b * NTOPK + i] * V[((size_t)b * NL + tt) * ND + d];
    }
    O16[e] = __float2half_rn(s);
}

__global__ void decomp_kernel(const float* __restrict__ X, float* __restrict__ Of,
                              __half* O16)
{
    size_t e = (size_t)blockIdx.x * blockDim.x + threadIdx.x;
    if (e >= (size_t)NBLD) return;
    int d = (int)(e & (ND - 1));
    size_t row = e >> 9;
    int b = (int)(row / NL);
    int t = (int)(row - (size_t)b * NL);
    const float* Xb = X + (size_t)b * NL * ND + d;
    float s = 0.f;
    #pragma unroll
    for (int u = -12; u <= 12; u++) {
        int tt = t + u;
        tt = tt < 0 ? 0 : (tt >= NL ? NL - 1 : tt);
        s += Xb[(size_t)tt * ND];
    }
    float v = X[e] - s * (1.f / 25.f);
    if (Of)  Of[e]  = v;
    if (O16) O16[e] = __float2half_rn(v);
}

// ------------------------------- host side -----------------------------------
#define GETSYM(var, sym) do{ cudaGetSymbolAddress((void**)&var, sym); }while(0)

extern "C" void kernel_launch(void* const* d_in, const int* in_sizes, int n_in,
                              void* d_out, int out_size)
{
    const float* x_s      = (const float*)d_in[0];
    const float* x_w      = (const float*)d_in[1];
    const float* wc1_W    = (const float*)d_in[2];
    const float* wc1_b    = (const float*)d_in[3];
    const float* wc2_W    = (const float*)d_in[4];
    const float* wc2_b    = (const float*)d_in[5];
    const float* attn_W   = (const float*)d_in[6];
    const float* attn_b   = (const float*)d_in[7];
    const float* wc1_proj = (const float*)d_in[8];
    const float* wc2_proj = (const float*)d_in[9];
    const float* conv1_W  = (const float*)d_in[10];
    const float* conv2_W  = (const float*)d_in[11];
    float* out  = (float*)d_out;
    float* out2 = out + NBLD;

    float *pv, *pxs, *pxs2, *ptmp, *pmean;
    GETSYM(pv, g_v); GETSYM(pxs, g_xs); GETSYM(pxs2, g_xs2);
    GETSYM(ptmp, g_tmp); GETSYM(pmean, g_mean);
    __half *wf, *pweh, *pwel;
    GETSYM(wf, g_wf); GETSYM(pweh, g_weh); GETSYM(pwel, g_wel);
    __half *pfXWh,*pfXWl,*pfXSI,*pfQ,*pfK,*pfO,*pfXSa,*pfXS2,*pfXW1h,*pfXW1l,*pfXSB,*pfH;
    GETSYM(pfXWh, fXWh);  GETSYM(pfXWl, fXWl);
    GETSYM(pfXSI, fXSI);
    GETSYM(pfQ, fQ);      GETSYM(pfK, fK);    GETSYM(pfO, fO);
    GETSYM(pfXSa, fXSa);  GETSYM(pfXS2, fXS2);
    GETSYM(pfXW1h, fXW1h);GETSYM(pfXW1l, fXW1l);
    GETSYM(pfXSB, fXSB);  GETSYM(pfH, fH);

    cudaFuncSetAttribute(gemm_s,        cudaFuncAttributeMaxDynamicSharedMemorySize, 2*SSTG);
    cudaFuncSetAttribute(embed_f16<3>,  cudaFuncAttributeMaxDynamicSharedMemorySize, 2*65536);
    cudaFuncSetAttribute(embed_f16<1>,  cudaFuncAttributeMaxDynamicSharedMemorySize, 2*32768);
    cudaFuncSetAttribute(corr_f16,      cudaFuncAttributeMaxDynamicSharedMemorySize, 2*SSTG);

    const int nEB = (NBLD + 255) / 256;
    dim3 corrG(12, 12, NB);
    dim3 embG(4, 192);

    auto G = [&](const __half* A, int woff, const float* bias, const float* R,
                 float* Cf, __half* C16, int N, int K, int relu){
        dim3 g(N >> 7, 192);
        gemm_s<<<g, 256, 2*SSTG>>>(A, wf + (size_t)woff * DDW, bias, R, Cf, C16, N, K, relu);
    };

    // ---- conversions --------------------------------------------------------
    cvt_f16s<<<1024,256>>>(wc1_W,  wf +  0*(size_t)DDW, DDW);
    cvt_f16s<<<1024,256>>>(attn_W, wf +  4*(size_t)DDW, DDW);
    cvt_f16s<<<1024,256>>>(wc2_W,  wf +  8*(size_t)DDW, DDW);
    cvt_f16s<<<1024,256>>>(conv1_W,wf + 12*(size_t)DDW, DDW);
    cvt_f16s<<<1024,256>>>(conv2_W,wf + 16*(size_t)DDW, DDW);
    for (int j = 0; j < 3; j++){
        cvt_proj_f16<<<(DDW+255)/256,256>>>(wc1_proj + j, pweh + (size_t)j*DDW,     pwel + (size_t)j*DDW);
        cvt_proj_f16<<<(DDW+255)/256,256>>>(wc2_proj + j, pweh + (size_t)(3+j)*DDW, pwel + (size_t)(3+j)*DDW);
    }
    cvt_f16hl<<<(NBLD/4+255)/256,256>>>(x_w, pfXWh, pfXWl, NBLD/4);
    cvt_f16s<<<(NBLD/4+255)/256,256>>>(x_s, pfXSI, NBLD/4);

    // ---- stage A: x_s += attn(q=x_w, k=v=x_s, wc1) --------------------------
    G(pfXWh, 0, wc1_b,        nullptr, nullptr, pfQ, ND, ND, 0);
    G(pfXSI, 1, wc1_b + ND,   nullptr, nullptr, pfK, ND, ND, 0);
    G(pfXSI, 2, wc1_b + 2*ND, nullptr, pv,      nullptr, ND, ND, 0);
    cudaMemsetAsync(pmean, 0, NB*NL*sizeof(float), 0);
    corr_f16<<<corrG, 256, 2*SSTG>>>(pfQ, pfK);
    topk_kernel<<<1, 512>>>();
    roll_kernel<<<nEB, 256>>>(pv, pfO);
    G(pfO, 3, wc1_b + 3*ND, x_s, pxs, pfXSa, ND, ND, 0);

    // ---- stage B: xw1 = token_embed(x_w, wc1_proj)  (3-term fp16) -----------
    embed_f16<3><<<embG, 256, 2*65536>>>(pfXWh, pfXWl, pweh, pwel,
                                         nullptr, pfXW1h, pfXW1l);

    // ---- stage C: xs += attn(xs, xs, xs, attn_W) ----------------------------
    G(pfXSa, 4, attn_b,        nullptr, nullptr, pfQ, ND, ND, 0);
    G(pfXSa, 5, attn_b + ND,   nullptr, nullptr, pfK, ND, ND, 0);
    G(pfXSa, 6, attn_b + 2*ND, nullptr, pv,      nullptr, ND, ND, 0);
    cudaMemsetAsync(pmean, 0, NB*NL*sizeof(float), 0);
    corr_f16<<<corrG, 256, 2*SSTG>>>(pfQ, pfK);
    topk_kernel<<<1, 512>>>();
    roll_kernel<<<nEB, 256>>>(pv, pfO);
    G(pfO, 7, attn_b + 3*ND, pxs, pxs, nullptr, ND, ND, 0);

    // ---- stage D: xs2 = series_decomp(xs) -----------------------------------
    decomp_kernel<<<nEB, 256>>>(pxs, pxs2, pfXS2);

    // ---- stage E: xs2' = xs2 + attn(q=xw1, k=v=xs2, wc2) --------------------
    G(pfXW1h, 8,  wc2_b,        nullptr, nullptr, pfQ, ND, ND, 0);
    G(pfXS2,  9,  wc2_b + ND,   nullptr, nullptr, pfK, ND, ND, 0);
    G(pfXS2,  10, wc2_b + 2*ND, nullptr, pv,      nullptr, ND, ND, 0);
    cudaMemsetAsync(pmean, 0, NB*NL*sizeof(float), 0);
    corr_f16<<<corrG, 256, 2*SSTG>>>(pfQ, pfK);
    topk_kernel<<<1, 512>>>();
    roll_kernel<<<nEB, 256>>>(pv, pfO);
    G(pfO, 11, wc2_b + 3*ND, pxs2, ptmp, pfXSB, ND, ND, 0);

    // ---- stage F: x_w_new = token_embed(xw1, wc2_proj) -> out2 (1-term) -----
    embed_f16<1><<<embG, 256, 2*32768>>>(pfXW1h, nullptr, pweh + 3*(size_t)DDW, nullptr,
                                         out2, nullptr, nullptr);

    // ---- stage G: FFN + final series_decomp -> out --------------------------
    G(pfXSB, 12, nullptr, nullptr, nullptr, pfH, NDFF, ND,   1);
    G(pfH,   16, nullptr, ptmp,    pv,      nullptr, ND, NDFF, 0);
    decomp_kernel<<<nEB, 256>>>(pv, out, nullptr);
}

// round 9
// speedup vs baseline: 7.6034x; 1.2602x over previous
#include <cuda_runtime.h>
#include <cuda_fp16.h>
#include <cstdint>
#include <math.h>

#define NB    16
#define NL    1536
#define ND    512
#define NDFF  2048
#define NTOPK 7
#define NBLD  (NB*NL*ND)
#define NH    (NB*NL*NDFF)
#define DDW   262144            // 512*512

// ------------------------------- scratch ------------------------------------
__device__ float g_xs[NBLD];
__device__ float g_xs2[NBLD];
__device__ float g_tmp[NBLD];
__device__ float g_v32[NBLD];   // spare fp32 (FFN out)
__device__ float g_mean[NB*NL];
__device__ int   g_idx[NTOPK];
__device__ float g_wt[NB*NTOPK];

// fp16 arenas
__device__ __half g_wf[20*DDW];   // wc1(4) attn(4) wc2(4) conv1(4) conv2(4)
__device__ __half g_weh[6*DDW];   // embed weights (wc1_proj 0-2, wc2_proj 3-5)
__device__ __half fXW[NBLD];
__device__ __half fXSI[NBLD];
__device__ __half fQ[NBLD], fK[NBLD], fV[NBLD], fO[NBLD];
__device__ __half fXSa[NBLD], fXS2[NBLD];
__device__ __half fXW1[NBLD];
__device__ __half fXSB[NBLD];
__device__ __half fH[NH];

// ------------------------------- helpers -------------------------------------
__device__ __forceinline__ uint32_t smem_u32(const void* p){
    uint32_t a;
    asm("{ .reg .u64 t; cvta.to.shared.u64 t, %1; cvt.u32.u64 %0, t; }":"=r"(a):"l"(p));
    return a;
}
__device__ __forceinline__ void cp16(uint32_t s, const void* g){
    asm volatile("cp.async.cg.shared.global [%0], [%1], 16;"::"r"(s),"l"(g));
}
__device__ __forceinline__ void cp_commit(){
    asm volatile("cp.async.commit_group;":::"memory");
}
__device__ __forceinline__ void ldm4(uint32_t* r, uint32_t a){
    asm volatile("ldmatrix.sync.aligned.m8n8.x4.shared.b16 {%0,%1,%2,%3}, [%4];"
        : "=r"(r[0]),"=r"(r[1]),"=r"(r[2]),"=r"(r[3]) : "r"(a));
}
__device__ __forceinline__ void mma16816f(float* c, const uint32_t* a, uint32_t b0, uint32_t b1){
    asm volatile("mma.sync.aligned.m16n8k16.row.col.f32.f16.f16.f32 "
        "{%0,%1,%2,%3},{%4,%5,%6,%7},{%8,%9},{%0,%1,%2,%3};"
        : "+f"(c[0]),"+f"(c[1]),"+f"(c[2]),"+f"(c[3])
        : "r"(a[0]),"r"(a[1]),"r"(a[2]),"r"(a[3]), "r"(b0),"r"(b1));
}
#define SWZ(o) ((o) ^ (((o) >> 3) & 0x70))
#define SSTG 32768u

#define WARP_SETUP() \
    int wm = wid >> 2, wn = wid & 3; \
    int rowA = (wm << 6) + (lane & 15); \
    int rowB = (wn << 5) + (lane & 15); \
    uint32_t sA = rowA & 7, sB = rowB & 7, cq = lane >> 4; \
    uint32_t aB[4], bB[2]; \
    _Pragma("unroll") for (int mi = 0; mi < 4; mi++) aB[mi] = (uint32_t)(rowA + (mi<<4)) * 128; \
    _Pragma("unroll") for (int nj = 0; nj < 2; nj++) bB[nj] = (uint32_t)(rowB + (nj<<4)) * 128; \
    float acc[4][4][4]; \
    _Pragma("unroll") for (int mi = 0; mi < 4; mi++) \
        _Pragma("unroll") for (int ni = 0; ni < 4; ni++) \
            _Pragma("unroll") for (int e2 = 0; e2 < 4; e2++) acc[mi][ni][e2] = 0.f;

#define MMA_CHUNK_1T(stgbase) do{ \
    _Pragma("unroll") \
    for (int ks = 0; ks < 4; ks++){ \
        uint32_t ah[4][4], bh[2][4]; \
        uint32_t ca = ((((ks<<1)|cq) ^ sA) << 4); \
        uint32_t cb = ((((ks<<1)|cq) ^ sB) << 4); \
        _Pragma("unroll") \
        for (int mi = 0; mi < 4; mi++) ldm4(ah[mi], (stgbase) + aB[mi] + ca); \
        _Pragma("unroll") \
        for (int nj = 0; nj < 2; nj++) ldm4(bh[nj], (stgbase) + bB[nj] + cb + 16384); \
        _Pragma("unroll") \
        for (int mi = 0; mi < 4; mi++) \
            _Pragma("unroll") \
            for (int ni = 0; ni < 4; ni++){ \
                uint32_t g = ni >> 1, s = ni & 1; \
                mma16816f(acc[mi][ni], ah[mi], bh[g][s], bh[g][s+2]); \
            } \
    } \
}while(0)

// ------------------------------- single-term fp16 GEMM -----------------------
// C[m,n] = act( sum_k A[m,k]*W[n,k] + bias[n] + R[m,n] )
// If C16b != null: merged-output mode; column block j=n>>9 routes to
// {C16, C16b, C16c}[j] at row stride 512.
__global__ void __launch_bounds__(256,2)
gemm_s(const __half* __restrict__ A, const __half* __restrict__ W,
       const float* __restrict__ bias, const float* __restrict__ R,
       float* Cf, __half* C16, __half* C16b, __half* C16c,
       int N, int K, int relu)
{
    extern __shared__ char smem[];
    uint32_t sb = smem_u32(smem);
    int tid = threadIdx.x, wid = tid >> 5, lane = tid & 31;
    int m0 = blockIdx.y << 7, n0 = blockIdx.x << 7;

    size_t aoff[4], boff[4];
    uint32_t soff[4];
    #pragma unroll
    for (int i = 0; i < 4; i++){
        int idx = tid + (i << 8);
        int r = idx >> 3, u = idx & 7;
        aoff[i] = (size_t)(m0 + r) * K + u * 8;
        boff[i] = (size_t)(n0 + r) * K + u * 8;
        soff[i] = SWZ((uint32_t)(r * 128 + u * 16));
    }
    WARP_SETUP();

    int nch = K >> 6;
    {
        #pragma unroll
        for (int i = 0; i < 4; i++){
            cp16(sb + soff[i],         A + aoff[i]);
            cp16(sb + 16384 + soff[i], W + boff[i]);
        }
        cp_commit();
    }
    for (int c = 0; c < nch; c++){
        if (c + 1 < nch){
            uint32_t sp_ = sb + ((c+1)&1)*SSTG;
            size_t k0 = (size_t)(c+1) << 6;
            #pragma unroll
            for (int i = 0; i < 4; i++){
                cp16(sp_ + soff[i],         A + aoff[i] + k0);
                cp16(sp_ + 16384 + soff[i], W + boff[i] + k0);
            }
            cp_commit();
            asm volatile("cp.async.wait_group 1;":::"memory");
        } else {
            asm volatile("cp.async.wait_group 0;":::"memory");
        }
        __syncthreads();
        MMA_CHUNK_1T(sb + (c & 1)*SSTG);
        __syncthreads();
    }

    int gm = m0 + (wm << 6) + (lane >> 2);
    int gn = n0 + (wn << 5) + ((lane & 3) << 1);
    #pragma unroll
    for (int mi = 0; mi < 4; mi++)
        #pragma unroll
        for (int ni = 0; ni < 4; ni++)
            #pragma unroll
            for (int hh = 0; hh < 2; hh++){
                int rr = gm + (mi << 4) + hh * 8;
                int cc = gn + (ni << 3);
                float v0 = acc[mi][ni][hh*2+0];
                float v1 = acc[mi][ni][hh*2+1];
                if (bias){ v0 += bias[cc]; v1 += bias[cc+1]; }
                if (C16b){
                    int j = cc >> 9, c2 = cc & 511;
                    __half* dst = (j == 0) ? C16 : ((j == 1) ? C16b : C16c);
                    *reinterpret_cast<__half2*>(dst + (size_t)rr * 512 + c2) =
                        __floats2half2_rn(v0, v1);
                } else {
                    size_t o = (size_t)rr * N + cc;
                    if (R){ float2 r2 = *reinterpret_cast<const float2*>(R + o); v0 += r2.x; v1 += r2.y; }
                    if (relu){ v0 = fmaxf(v0, 0.f); v1 = fmaxf(v1, 0.f); }
                    if (Cf)  *reinterpret_cast<float2*>(Cf + o)  = make_float2(v0, v1);
                    if (C16) *reinterpret_cast<__half2*>(C16 + o) = __floats2half2_rn(v0, v1);
                }
            }
}

// --------------------------- fused token-embed (single-term) -----------------
// C[m,n] = sum_tap sum_k A[shift(m,tap-1),k]*Wtap[n,k]; 24 chunks over 3 taps.
__global__ void __launch_bounds__(256,2)
embed_f16(const __half* __restrict__ A, const __half* __restrict__ B,
          float* Cf, __half* Ch)
{
    extern __shared__ char smem[];
    uint32_t sb = smem_u32(smem);
    int tid = threadIdx.x, wid = tid >> 5, lane = tid & 31;
    int m0 = blockIdx.y << 7, n0 = blockIdx.x << 7;

    size_t aoff0[4], boff[4];
    int dm1[4], dp1[4];
    uint32_t soff[4];
    #pragma unroll
    for (int i = 0; i < 4; i++){
        int idx = tid + (i << 8);
        int r = idx >> 3, u = idx & 7;
        int am = m0 + r;
        int b = am / NL;
        int t = am - b * NL;
        aoff0[i] = (size_t)am * ND + u * 8;
        dm1[i] = ((t == 0    ? NL - 1 : t - 1) - t) * ND;
        dp1[i] = ((t == NL-1 ? 0      : t + 1) - t) * ND;
        boff[i] = (size_t)(n0 + r) * ND + u * 8;
        soff[i] = SWZ((uint32_t)(r * 128 + u * 16));
    }
    WARP_SETUP();

    #define ELOAD(stage, c_) do{ \
        int tap_ = (c_) >> 3; \
        int kb_ = ((c_) & 7) << 6; \
        size_t bo_ = (size_t)tap_ * DDW + kb_; \
        uint32_t sp_ = sb + (stage)*SSTG; \
        _Pragma("unroll") \
        for (int i_ = 0; i_ < 4; i_++){ \
            long ao_ = (long)aoff0[i_] + (tap_ == 0 ? dm1[i_] : (tap_ == 2 ? dp1[i_] : 0)) + kb_; \
            cp16(sp_ + soff[i_],          A + ao_); \
            cp16(sp_ + 16384 + soff[i_],  B + boff[i_] + bo_); \
        } \
        cp_commit(); \
    }while(0)

    ELOAD(0, 0);
    for (int c = 0; c < 24; c++){
        if (c + 1 < 24){
            ELOAD((c+1)&1, c+1);
            asm volatile("cp.async.wait_group 1;":::"memory");
        } else {
            asm volatile("cp.async.wait_group 0;":::"memory");
        }
        __syncthreads();
        MMA_CHUNK_1T(sb + (c & 1)*SSTG);
        __syncthreads();
    }
    #undef ELOAD

    int gm = m0 + (wm << 6) + (lane >> 2);
    int gn = n0 + (wn << 5) + ((lane & 3) << 1);
    #pragma unroll
    for (int mi = 0; mi < 4; mi++)
        #pragma unroll
        for (int ni = 0; ni < 4; ni++)
            #pragma unroll
            for (int hh = 0; hh < 2; hh++){
                int rr = gm + (mi << 4) + hh * 8;
                int cc = gn + (ni << 3);
                float v0 = acc[mi][ni][hh*2+0];
                float v1 = acc[mi][ni][hh*2+1];
                size_t o = (size_t)rr * ND + cc;
                if (Cf) *reinterpret_cast<float2*>(Cf + o) = make_float2(v0, v1);
                if (Ch) *reinterpret_cast<__half2*>(Ch + o) = __floats2half2_rn(v0, v1);
            }
}

// --------------------------- correlation (fp16, 1-term) ----------------------
__global__ void __launch_bounds__(256,2)
corr_f16(const __half* __restrict__ Qf, const __half* __restrict__ Kf)
{
    extern __shared__ char smem[];
    uint32_t sb = smem_u32(smem);
    int tid = threadIdx.x, wid = tid >> 5, lane = tid & 31;
    int bb = blockIdx.z;
    size_t base = (size_t)bb * NL * ND;
    int m0 = blockIdx.y << 7, n0 = blockIdx.x << 7;

    size_t aoff[4], boff[4];
    uint32_t soff[4];
    #pragma unroll
    for (int i = 0; i < 4; i++){
        int idx = tid + (i << 8);
        int r = idx >> 3, u = idx & 7;
        aoff[i] = base + (size_t)(m0 + r) * ND + u * 8;
        boff[i] = base + (size_t)(n0 + r) * ND + u * 8;
        soff[i] = SWZ((uint32_t)(r * 128 + u * 16));
    }
    WARP_SETUP();

    {
        #pragma unroll
        for (int i = 0; i < 4; i++){
            cp16(sb + soff[i],          Qf + aoff[i]);
            cp16(sb + 16384 + soff[i],  Kf + boff[i]);
        }
        cp_commit();
    }
    for (int c = 0; c < 8; c++){
        if (c + 1 < 8){
            uint32_t sp_ = sb + ((c+1)&1)*SSTG;
            size_t k0 = (size_t)(c+1) << 6;
            #pragma unroll
            for (int i = 0; i < 4; i++){
                cp16(sp_ + soff[i],          Qf + aoff[i] + k0);
                cp16(sp_ + 16384 + soff[i],  Kf + boff[i] + k0);
            }
            cp_commit();
            asm volatile("cp.async.wait_group 1;":::"memory");
        } else {
            asm volatile("cp.async.wait_group 0;":::"memory");
        }
        __syncthreads();
        MMA_CHUNK_1T(sb + (c & 1)*SSTG);
        __syncthreads();
    }

    float* bins = reinterpret_cast<float*>(smem);
    if (tid < 255) bins[tid] = 0.f;
    __syncthreads();

    int lm = (wm << 6) + (lane >> 2);
    int ln = (wn << 5) + ((lane & 3) << 1);
    #pragma unroll
    for (int mi = 0; mi < 4; mi++)
        #pragma unroll
        for (int ni = 0; ni < 4; ni++)
            #pragma unroll
            for (int hh = 0; hh < 2; hh++){
                int rr = lm + (mi << 4) + hh * 8;
                int cc = ln + (ni << 3);
                atomicAdd(&bins[rr - cc + 127],     acc[mi][ni][hh*2+0]);
                atomicAdd(&bins[rr - cc - 1 + 127], acc[mi][ni][hh*2+1]);
            }
    __syncthreads();
    if (tid < 255){
        int tau = m0 - n0 + tid - 127;
        tau %= NL; if (tau < 0) tau += NL;
        atomicAdd(&g_mean[bb * NL + tau], bins[tid] * (1.f / 512.f));
    }
}

// ------------------------------ small kernels --------------------------------
__global__ void cvt_f16s(const float* __restrict__ x, __half* __restrict__ o, int n4)
{
    int i = blockIdx.x * blockDim.x + threadIdx.x;
    if (i >= n4) return;
    float4 v = reinterpret_cast<const float4*>(x)[i];
    __half2* op = reinterpret_cast<__half2*>(o);
    op[2*i]   = __floats2half2_rn(v.x, v.y);
    op[2*i+1] = __floats2half2_rn(v.z, v.w);
}

// de-stride token-embed weights: dst[n*512+k] = src[n*1536 + k*3]
__global__ void cvt_proj_f16(const float* __restrict__ src, __half* __restrict__ h)
{
    int e = blockIdx.x * blockDim.x + threadIdx.x;
    if (e >= DDW) return;
    int n = e >> 9, k = e & 511;
    h[e] = __float2half_rn(src[n * 1536 + k * 3]);
}

__global__ void topk_kernel()
{
    __shared__ float gv[NL];
    __shared__ float rv[512];
    __shared__ int   ri[512];
    __shared__ int   sidx[NTOPK];
    int tid = threadIdx.x;
    for (int t = tid; t < NL; t += 512) {
        float s = 0.f;
        for (int b = 0; b < NB; b++) s += g_mean[b * NL + t];
        gv[t] = s;
    }
    __syncthreads();
    for (int it = 0; it < NTOPK; it++) {
        float bv = -INFINITY; int bi = 0x7fffffff;
        for (int t = tid; t < NL; t += 512) {
            float v = gv[t];
            if (v > bv || (v == bv && t < bi)) { bv = v; bi = t; }
        }
        rv[tid] = bv; ri[tid] = bi;
        __syncthreads();
        for (int s = 256; s > 0; s >>= 1) {
            if (tid < s) {
                if (rv[tid+s] > rv[tid] || (rv[tid+s] == rv[tid] && ri[tid+s] < ri[tid])) {
                    rv[tid] = rv[tid+s]; ri[tid] = ri[tid+s];
                }
            }
            __syncthreads();
        }
        if (tid == 0) { sidx[it] = ri[0]; gv[ri[0]] = -INFINITY; }
        __syncthreads();
    }
    if (tid < NTOPK) g_idx[tid] = sidx[tid];
    if (tid < NB) {
        float vals[NTOPK];
        float mx = -INFINITY;
        for (int i = 0; i < NTOPK; i++) {
            vals[i] = g_mean[tid * NL + sidx[i]];
            mx = fmaxf(mx, vals[i]);
        }
        float s = 0.f;
        for (int i = 0; i < NTOPK; i++) { vals[i] = expf(vals[i] - mx); s += vals[i]; }
        float inv = 1.f / s;
        for (int i = 0; i < NTOPK; i++) g_wt[tid * NTOPK + i] = vals[i] * inv;
    }
}

// time-delay aggregation on fp16 V, half2-vectorized
__global__ void roll_kernel(const __half* __restrict__ V16, __half* __restrict__ O16)
{
    int e = blockIdx.x * blockDim.x + threadIdx.x;
    if (e >= NBLD/2) return;
    int dh = e & 255;
    int row = e >> 8;
    int b = row / NL;
    int t = row - b * NL;
    float sx = 0.f, sy = 0.f;
    #pragma unroll
    for (int i = 0; i < NTOPK; i++) {
        int tt = t + g_idx[i];
        if (tt >= NL) tt -= NL;
        __half2 v = *reinterpret_cast<const __half2*>(V16 + ((size_t)(b*NL + tt))*ND + dh*2);
        float2 vf = __half22float2(v);
        float w = g_wt[b * NTOPK + i];
        sx += w * vf.x; sy += w * vf.y;
    }
    *reinterpret_cast<__half2*>(O16 + (size_t)row * ND + dh*2) = __floats2half2_rn(sx, sy);
}

// series_decomp, sliding-window, 8 outputs/thread
__global__ void decomp_kernel(const float* __restrict__ X, float* __restrict__ Of,
                              __half* O16)
{
    int i = blockIdx.x * blockDim.x + threadIdx.x;
    if (i >= NBLD/8) return;
    int d = i & 511;
    int c = i >> 9;
    int b = c / (NL/8);
    int tb = (c - b * (NL/8)) * 8;
    const float* Xb = X + (size_t)b * NL * ND + d;

    float acc = 0.f;
    #pragma unroll
    for (int u = -12; u <= 12; u++){
        int t = tb + u;
        t = t < 0 ? 0 : (t >= NL ? NL - 1 : t);
        acc += Xb[(size_t)t * ND];
    }
    #pragma unroll
    for (int j = 0; j < 8; j++){
        int t = tb + j;
        float x = Xb[(size_t)t * ND];
        float v = x - acc * (1.f / 25.f);
        size_t e = ((size_t)b * NL + t) * ND + d;
        if (Of)  Of[e]  = v;
        if (O16) O16[e] = __float2half_rn(v);
        int ta = t + 13; ta = ta >= NL ? NL - 1 : ta;
        int ts = t - 12; ts = ts < 0 ? 0 : ts;
        acc += Xb[(size_t)ta * ND] - Xb[(size_t)ts * ND];
    }
}

// ------------------------------- host side -----------------------------------
#define GETSYM(var, sym) do{ cudaGetSymbolAddress((void**)&var, sym); }while(0)

extern "C" void kernel_launch(void* const* d_in, const int* in_sizes, int n_in,
                              void* d_out, int out_size)
{
    const float* x_s      = (const float*)d_in[0];
    const float* x_w      = (const float*)d_in[1];
    const float* wc1_W    = (const float*)d_in[2];
    const float* wc1_b    = (const float*)d_in[3];
    const float* wc2_W    = (const float*)d_in[4];
    const float* wc2_b    = (const float*)d_in[5];
    const float* attn_W   = (const float*)d_in[6];
    const float* attn_b   = (const float*)d_in[7];
    const float* wc1_proj = (const float*)d_in[8];
    const float* wc2_proj = (const float*)d_in[9];
    const float* conv1_W  = (const float*)d_in[10];
    const float* conv2_W  = (const float*)d_in[11];
    float* out  = (float*)d_out;
    float* out2 = out + NBLD;

    float *pxs, *pxs2, *ptmp, *pv32, *pmean;
    GETSYM(pxs, g_xs); GETSYM(pxs2, g_xs2); GETSYM(ptmp, g_tmp);
    GETSYM(pv32, g_v32); GETSYM(pmean, g_mean);
    __half *wf, *pweh;
    GETSYM(wf, g_wf); GETSYM(pweh, g_weh);
    __half *pfXW,*pfXSI,*pfQ,*pfK,*pfV,*pfO,*pfXSa,*pfXS2,*pfXW1,*pfXSB,*pfH;
    GETSYM(pfXW, fXW);   GETSYM(pfXSI, fXSI);
    GETSYM(pfQ, fQ);     GETSYM(pfK, fK);   GETSYM(pfV, fV);   GETSYM(pfO, fO);
    GETSYM(pfXSa, fXSa); GETSYM(pfXS2, fXS2);
    GETSYM(pfXW1, fXW1); GETSYM(pfXSB, fXSB); GETSYM(pfH, fH);

    cudaFuncSetAttribute(gemm_s,    cudaFuncAttributeMaxDynamicSharedMemorySize, 2*SSTG);
    cudaFuncSetAttribute(embed_f16, cudaFuncAttributeMaxDynamicSharedMemorySize, 2*SSTG);
    cudaFuncSetAttribute(corr_f16,  cudaFuncAttributeMaxDynamicSharedMemorySize, 2*SSTG);

    const int nRB = (NBLD/2 + 255) / 256;
    const int nDB = (NBLD/8 + 255) / 256;
    dim3 corrG(12, 12, NB);
    dim3 embG(4, 192);

    // plain GEMM: fp32/fp16 single-output, optional bias/R/relu
    auto G = [&](const __half* A, int woff, const float* bias, const float* R,
                 float* Cf, __half* C16, int N, int K, int relu){
        dim3 g(N >> 7, 192);
        gemm_s<<<g, 256, 2*SSTG>>>(A, wf + (size_t)woff * DDW, bias, R,
                                   Cf, C16, nullptr, nullptr, N, K, relu);
    };
    // merged-output GEMM: N = 512*nout, outputs routed per 512-column block
    auto Gm = [&](const __half* A, int woff, const float* bias,
                  __half* C0, __half* C1, __half* C2, int N){
        dim3 g(N >> 7, 192);
        gemm_s<<<g, 256, 2*SSTG>>>(A, wf + (size_t)woff * DDW, bias, nullptr,
                                   nullptr, C0, C1, C2 ? C2 : C1, N, ND, 0);
    };

    // ---- conversions --------------------------------------------------------
    cvt_f16s<<<1024,256>>>(wc1_W,  wf +  0*(size_t)DDW, DDW);
    cvt_f16s<<<1024,256>>>(attn_W, wf +  4*(size_t)DDW, DDW);
    cvt_f16s<<<1024,256>>>(wc2_W,  wf +  8*(size_t)DDW, DDW);
    cvt_f16s<<<1024,256>>>(conv1_W,wf + 12*(size_t)DDW, DDW);
    cvt_f16s<<<1024,256>>>(conv2_W,wf + 16*(size_t)DDW, DDW);
    for (int j = 0; j < 3; j++){
        cvt_proj_f16<<<(DDW+255)/256,256>>>(wc1_proj + j, pweh + (size_t)j*DDW);
        cvt_proj_f16<<<(DDW+255)/256,256>>>(wc2_proj + j, pweh + (size_t)(3+j)*DDW);
    }
    cvt_f16s<<<(NBLD/4+255)/256,256>>>(x_w, pfXW,  NBLD/4);
    cvt_f16s<<<(NBLD/4+255)/256,256>>>(x_s, pfXSI, NBLD/4);

    // ---- stage A: x_s += attn(q=x_w, k=v=x_s, wc1) --------------------------
    G (pfXW,  0, wc1_b,      nullptr, nullptr, pfQ, ND, ND, 0);
    Gm(pfXSI, 1, wc1_b + ND, pfK, pfV, nullptr, 1024);
    cudaMemsetAsync(pmean, 0, NB*NL*sizeof(float), 0);
    corr_f16<<<corrG, 256, 2*SSTG>>>(pfQ, pfK);
    topk_kernel<<<1, 512>>>();
    roll_kernel<<<nRB, 256>>>(pfV, pfO);
    G(pfO, 3, wc1_b + 3*ND, x_s, pxs, pfXSa, ND, ND, 0);

    // ---- stage B: xw1 = token_embed(x_w, wc1_proj) --------------------------
    embed_f16<<<embG, 256, 2*SSTG>>>(pfXW, pweh, nullptr, pfXW1);

    // ---- stage C: xs += attn(xs, xs, xs, attn_W) ----------------------------
    Gm(pfXSa, 4, attn_b, pfQ, pfK, pfV, 1536);
    cudaMemsetAsync(pmean, 0, NB*NL*sizeof(float), 0);
    corr_f16<<<corrG, 256, 2*SSTG>>>(pfQ, pfK);
    topk_kernel<<<1, 512>>>();
    roll_kernel<<<nRB, 256>>>(pfV, pfO);
    G(pfO, 7, attn_b + 3*ND, pxs, pxs, nullptr, ND, ND, 0);

    // ---- stage D: xs2 = series_decomp(xs) -----------------------------------
    decomp_kernel<<<nDB, 256>>>(pxs, pxs2, pfXS2);

    // ---- stage E: xs2' = xs2 + attn(q=xw1, k=v=xs2, wc2) --------------------
    G (pfXW1, 8, wc2_b,      nullptr, nullptr, pfQ, ND, ND, 0);
    Gm(pfXS2, 9, wc2_b + ND, pfK, pfV, nullptr, 1024);
    cudaMemsetAsync(pmean, 0, NB*NL*sizeof(float), 0);
    corr_f16<<<corrG, 256, 2*SSTG>>>(pfQ, pfK);
    topk_kernel<<<1, 512>>>();
    roll_kernel<<<nRB, 256>>>(pfV, pfO);
    G(pfO, 11, wc2_b + 3*ND, pxs2, ptmp, pfXSB, ND, ND, 0);

    // ---- stage F: x_w_new = token_embed(xw1, wc2_proj) -> out2 --------------
    embed_f16<<<embG, 256, 2*SSTG>>>(pfXW1, pweh + 3*(size_t)DDW, out2, nullptr);

    // ---- stage G: FFN + final series_decomp -> out --------------------------
    G(pfXSB, 12, nullptr, nullptr, nullptr, pfH, NDFF, ND,   1);
    G(pfH,   16, nullptr, ptmp,    pv32,    nullptr, ND, NDFF, 0);
    decomp_kernel<<<nDB, 256>>>(pv32, out, nullptr);
}